// round 1
// baseline (speedup 1.0000x reference)
#include <cuda_runtime.h>
#include <cuda_bf16.h>
#include <cstdint>

#define NN 100000
#define NE 1600000
#define FD 128
#define NG 512
#define NC 10
#define NL 5
#define BN_EPS 1e-5f

// ---------------- scratch (device globals; no allocs allowed) ----------------
__device__ float g_P[NN * FD];        // node features (layer output)
__device__ float g_Q[NN * FD];        // scratch (agg result / gemm1 result)
__device__ float g_pooled[NG * FD];
__device__ float g_psum[250 * FD];
__device__ float g_psq[250 * FD];
__device__ float g_scale[FD];
__device__ float g_shift[FD];
__device__ int   g_cnt[NN];
__device__ int   g_off[NN + 1];
__device__ int   g_cur[NN];
__device__ int   g_csr[NE];
__device__ int   g_is64;              // 1 if edge_index/batch are int64

// ---------------- index-width detection ----------------
__global__ void detect_kernel(const unsigned* ei_words) {
    // int64 little-endian: high word of each element is 0 (values in [0,1e5))
    // int32: words are random node ids; 64 consecutive odd words all-zero is impossible.
    if (threadIdx.x == 0 && blockIdx.x == 0) {
        int is64 = 1;
        for (int i = 1; i < 64; i++) {
            if (ei_words[2 * i + 1] != 0u) { is64 = 0; break; }
        }
        g_is64 = is64;
    }
}

__device__ __forceinline__ int load_idx(const void* p, long long i) {
    if (g_is64) return (int)((const long long*)p)[i];
    return ((const int*)p)[i];
}

// ---------------- CSR build ----------------
__global__ void zero_cnt_kernel() {
    int i = blockIdx.x * blockDim.x + threadIdx.x;
    if (i < NN) g_cnt[i] = 0;
}

__global__ void count_kernel(const void* ei) {
    int e = blockIdx.x * blockDim.x + threadIdx.x;
    if (e < NE) {
        int d = load_idx(ei, (long long)NE + e);
        atomicAdd(&g_cnt[d], 1);
    }
}

__global__ void scan_kernel() {
    __shared__ int wsum[32];
    __shared__ int totalS;
    __shared__ int carry;
    int tid = threadIdx.x, lane = tid & 31, wid = tid >> 5;
    if (tid == 0) carry = 0;
    __syncthreads();
    for (int base = 0; base < NN; base += 1024) {
        int i = base + tid;
        int v = (i < NN) ? g_cnt[i] : 0;
        int incl = v;
        #pragma unroll
        for (int d = 1; d < 32; d <<= 1) {
            int t = __shfl_up_sync(0xffffffffu, incl, d);
            if (lane >= d) incl += t;
        }
        if (lane == 31) wsum[wid] = incl;
        __syncthreads();
        if (wid == 0) {
            int wv = wsum[lane];
            int wincl = wv;
            #pragma unroll
            for (int d = 1; d < 32; d <<= 1) {
                int t = __shfl_up_sync(0xffffffffu, wincl, d);
                if (lane >= d) wincl += t;
            }
            wsum[lane] = wincl - wv;       // exclusive warp offset
            if (lane == 31) totalS = wincl; // chunk total
        }
        __syncthreads();
        if (i < NN) g_off[i] = carry + wsum[wid] + incl - v;
        __syncthreads();
        if (tid == 0) carry += totalS;
        __syncthreads();
    }
    if (threadIdx.x == 0) g_off[NN] = carry;
}

__global__ void copy_cur_kernel() {
    int i = blockIdx.x * blockDim.x + threadIdx.x;
    if (i < NN) g_cur[i] = g_off[i];
}

__global__ void fill_kernel(const void* ei) {
    int e = blockIdx.x * blockDim.x + threadIdx.x;
    if (e < NE) {
        int s = load_idx(ei, e);
        int d = load_idx(ei, (long long)NE + e);
        int pos = atomicAdd(&g_cur[d], 1);
        g_csr[pos] = s;
    }
}

// ---------------- edge aggregation: out[n] = x[n] + sum_{j->n} x[j] ----------------
__global__ void agg_kernel(const float* __restrict__ x, float* __restrict__ out) {
    int w = (blockIdx.x * blockDim.x + threadIdx.x) >> 5;
    int lane = threadIdx.x & 31;
    if (w >= NN) return;
    const float4* xv = (const float4*)x;
    float4 acc = xv[(size_t)w * 32 + lane];
    int s = g_off[w], e = g_off[w + 1];
    for (int i = s; i < e; i++) {
        int nb = __ldg(&g_csr[i]);
        float4 v = __ldg(&xv[(size_t)nb * 32 + lane]);
        acc.x += v.x; acc.y += v.y; acc.z += v.z; acc.w += v.w;
    }
    ((float4*)out)[(size_t)w * 32 + lane] = acc;
}

// ---------------- 128-wide GEMM: C = act( pre(A) @ W + bias ) ----------------
// pre(A): optional per-column affine + relu (fused batchnorm+relu on input)
// Tile: 128 rows x 128 cols x K=128, 256 threads, 8x8 per thread.
template <bool PRE_BN, bool OUT_RELU>
__global__ void gemm128_kernel(const float* __restrict__ A,
                               const float* __restrict__ W,
                               const float* __restrict__ bias,
                               const float* __restrict__ scale,
                               const float* __restrict__ shift,
                               float* __restrict__ C, int M) {
    extern __shared__ float smem[];
    float* As = smem;            // 128*128
    float* Bs = smem + 16384;    // 128*128
    int tid = threadIdx.x;
    int r0 = blockIdx.x * 128;

    #pragma unroll
    for (int i = 0; i < 16; i++) {
        int f4 = tid + i * 256;
        ((float4*)Bs)[f4] = ((const float4*)W)[f4];
    }
    #pragma unroll
    for (int i = 0; i < 16; i++) {
        int f4 = tid + i * 256;
        int row = f4 >> 5;
        int c4 = f4 & 31;
        float4 v = make_float4(0.f, 0.f, 0.f, 0.f);
        if (r0 + row < M)
            v = ((const float4*)(A + (size_t)(r0 + row) * 128))[c4];
        if (PRE_BN) {
            int c = c4 * 4;
            v.x = fmaxf(v.x * __ldg(&scale[c + 0]) + __ldg(&shift[c + 0]), 0.f);
            v.y = fmaxf(v.y * __ldg(&scale[c + 1]) + __ldg(&shift[c + 1]), 0.f);
            v.z = fmaxf(v.z * __ldg(&scale[c + 2]) + __ldg(&shift[c + 2]), 0.f);
            v.w = fmaxf(v.w * __ldg(&scale[c + 3]) + __ldg(&shift[c + 3]), 0.f);
        }
        ((float4*)As)[f4] = v;
    }
    __syncthreads();

    int tr = tid >> 4;   // 0..15 row block
    int tc = tid & 15;   // 0..15 col block
    float acc[8][8];
    #pragma unroll
    for (int i = 0; i < 8; i++)
        #pragma unroll
        for (int j = 0; j < 8; j++) acc[i][j] = 0.f;

    #pragma unroll 4
    for (int k = 0; k < 128; k++) {
        float a[8];
        #pragma unroll
        for (int i = 0; i < 8; i++) a[i] = As[(tr * 8 + i) * 128 + k];
        float4 b0 = *(float4*)(Bs + k * 128 + tc * 8);
        float4 b1 = *(float4*)(Bs + k * 128 + tc * 8 + 4);
        float b[8] = {b0.x, b0.y, b0.z, b0.w, b1.x, b1.y, b1.z, b1.w};
        #pragma unroll
        for (int i = 0; i < 8; i++)
            #pragma unroll
            for (int j = 0; j < 8; j++)
                acc[i][j] += a[i] * b[j];
    }

    float bb[8];
    #pragma unroll
    for (int j = 0; j < 8; j++) bb[j] = __ldg(&bias[tc * 8 + j]);

    #pragma unroll
    for (int i = 0; i < 8; i++) {
        int gr = r0 + tr * 8 + i;
        if (gr < M) {
            float o[8];
            #pragma unroll
            for (int j = 0; j < 8; j++) {
                o[j] = acc[i][j] + bb[j];
                if (OUT_RELU) o[j] = fmaxf(o[j], 0.f);
            }
            float4* dst = (float4*)(C + (size_t)gr * 128 + tc * 8);
            dst[0] = make_float4(o[0], o[1], o[2], o[3]);
            dst[1] = make_float4(o[4], o[5], o[6], o[7]);
        }
    }
}

// ---------------- BN column statistics (deterministic tree) ----------------
__global__ void colstats_kernel(const float* __restrict__ h) {
    int c = threadIdx.x;   // 128
    int b = blockIdx.x;    // 250 blocks, 400 rows each (exactly 100000)
    int r0 = b * 400;
    float s = 0.f, q = 0.f;
    for (int r = r0; r < r0 + 400; r += 4) {
        float v0 = h[(size_t)(r + 0) * 128 + c];
        float v1 = h[(size_t)(r + 1) * 128 + c];
        float v2 = h[(size_t)(r + 2) * 128 + c];
        float v3 = h[(size_t)(r + 3) * 128 + c];
        s += v0 + v1 + v2 + v3;
        q += v0 * v0 + v1 * v1 + v2 * v2 + v3 * v3;
    }
    g_psum[b * 128 + c] = s;
    g_psq[b * 128 + c] = q;
}

__global__ void bnfinalize_kernel(const float* __restrict__ gamma,
                                  const float* __restrict__ beta) {
    int c = threadIdx.x;
    float s = 0.f, q = 0.f;
    for (int b = 0; b < 250; b++) {
        s += g_psum[b * 128 + c];
        q += g_psq[b * 128 + c];
    }
    float mu = s / (float)NN;
    float var = q / (float)NN - mu * mu;
    float sc = gamma[c] * rsqrtf(var + BN_EPS);
    g_scale[c] = sc;
    g_shift[c] = beta[c] - mu * sc;
}

// ---------------- pooling + head ----------------
__global__ void zero_pool_kernel() {
    int i = blockIdx.x * blockDim.x + threadIdx.x;
    if (i < NG * FD) g_pooled[i] = 0.f;
}

__global__ void pool_kernel(const float* __restrict__ x, const void* batch) {
    int i = blockIdx.x * blockDim.x + threadIdx.x;  // N*128 threads
    int node = i >> 7;
    int c = i & 127;
    int g = load_idx(batch, node);
    atomicAdd(&g_pooled[g * 128 + c], x[i]);
}

__global__ void head_kernel(const float* __restrict__ W1,
                            const float* __restrict__ b1,
                            const float* __restrict__ W2,
                            const float* __restrict__ b2,
                            float* __restrict__ out) {
    __shared__ float pr[128];
    __shared__ float h1[128];
    int g = blockIdx.x;
    int t = threadIdx.x;
    pr[t] = g_pooled[g * 128 + t];
    __syncthreads();
    float s = b1[t];
    #pragma unroll 8
    for (int k = 0; k < 128; k++) s += pr[k] * W1[k * 128 + t];
    h1[t] = fmaxf(s, 0.f);
    __syncthreads();
    if (t < NC) {
        float o = b2[t];
        #pragma unroll 8
        for (int k = 0; k < 128; k++) o += h1[k] * W2[k * NC + t];
        out[g * NC + t] = o;
    }
}

// ---------------- launcher ----------------
extern "C" void kernel_launch(void* const* d_in, const int* in_sizes, int n_in,
                              void* d_out, int out_size) {
    const float* x       = (const float*)d_in[0];
    const void*  ei      = d_in[1];
    const void*  batch   = d_in[2];
    const float* conv_W1 = (const float*)d_in[3];
    const float* conv_b1 = (const float*)d_in[4];
    const float* conv_g  = (const float*)d_in[5];
    const float* conv_bt = (const float*)d_in[6];
    const float* conv_W2 = (const float*)d_in[7];
    const float* conv_b2 = (const float*)d_in[8];
    const float* head_W1 = (const float*)d_in[9];
    const float* head_b1 = (const float*)d_in[10];
    const float* head_W2 = (const float*)d_in[11];
    const float* head_b2 = (const float*)d_in[12];
    float* out = (float*)d_out;

    float *P, *Q, *scale, *shift;
    cudaGetSymbolAddress((void**)&P, g_P);
    cudaGetSymbolAddress((void**)&Q, g_Q);
    cudaGetSymbolAddress((void**)&scale, g_scale);
    cudaGetSymbolAddress((void**)&shift, g_shift);

    const int SMEM = 131072;
    cudaFuncSetAttribute(gemm128_kernel<false, false>,
                         cudaFuncAttributeMaxDynamicSharedMemorySize, SMEM);
    cudaFuncSetAttribute(gemm128_kernel<true, true>,
                         cudaFuncAttributeMaxDynamicSharedMemorySize, SMEM);

    // index-width detection
    detect_kernel<<<1, 1>>>((const unsigned*)ei);

    // CSR build (reused by all 5 layers)
    zero_cnt_kernel<<<(NN + 255) / 256, 256>>>();
    count_kernel<<<NE / 256, 256>>>(ei);
    scan_kernel<<<1, 1024>>>();
    copy_cur_kernel<<<(NN + 255) / 256, 256>>>();
    fill_kernel<<<NE / 256, 256>>>(ei);

    const int GEMM_GRID = (NN + 127) / 128;
    const float* xin = x;
    for (int l = 0; l < NL; l++) {
        // Q = xin + sum_neighbors xin
        agg_kernel<<<(NN * 32 + 255) / 256, 256>>>(xin, Q);
        // Q = Q @ W1[l] + b1[l]   (in-place, row-wise safe)
        gemm128_kernel<false, false><<<GEMM_GRID, 256, SMEM>>>(
            Q, conv_W1 + (size_t)l * FD * FD, conv_b1 + l * FD,
            nullptr, nullptr, Q, NN);
        // BN stats over Q
        colstats_kernel<<<250, 128>>>(Q);
        bnfinalize_kernel<<<1, 128>>>(conv_g + l * FD, conv_bt + l * FD);
        // P = relu( relu(BN(Q)) @ W2[l] + b2[l] )
        gemm128_kernel<true, true><<<GEMM_GRID, 256, SMEM>>>(
            Q, conv_W2 + (size_t)l * FD * FD, conv_b2 + l * FD,
            scale, shift, P, NN);
        xin = P;
    }

    // global_add_pool + head MLP
    zero_pool_kernel<<<(NG * FD + 255) / 256, 256>>>();
    pool_kernel<<<(NN * FD) / 256, 256>>>(P, batch);
    head_kernel<<<NG, 128>>>(head_W1, head_b1, head_W2, head_b2, out);
}

// round 3
// speedup vs baseline: 1.3979x; 1.3979x over previous
#include <cuda_runtime.h>
#include <cuda_bf16.h>
#include <cstdint>

#define NN 100000
#define NE 1600000
#define FD 128
#define NG 512
#define NC 10
#define NL 5
#define BN_EPS 1e-5f
#define SCAN_B 98          // ceil(NN/1024)
#define LDT 132            // padded smem stride (floats)

// ---------------- scratch (device globals; no allocs allowed) ----------------
__device__ float g_P[NN * FD];
__device__ float g_Q[NN * FD];
__device__ float g_pooled[NG * FD];
__device__ float g_psum[250 * FD];
__device__ float g_psq[250 * FD];
__device__ float g_scale[FD];
__device__ float g_shift[FD];
__device__ int   g_cnt[NN];
__device__ int   g_off[NN + 1];
__device__ int   g_cur[NN];
__device__ int   g_csr[NE];
__device__ int   g_bsum[SCAN_B];
__device__ int   g_boff[SCAN_B];
__device__ int   g_is64;

// ---------------- index-width detection ----------------
__global__ void detect_kernel(const unsigned* ei_words) {
    if (threadIdx.x == 0 && blockIdx.x == 0) {
        int is64 = 1;
        for (int i = 1; i < 64; i++) {
            if (ei_words[2 * i + 1] != 0u) { is64 = 0; break; }
        }
        g_is64 = is64;
    }
}

__device__ __forceinline__ int load_idx(const void* p, long long i) {
    if (g_is64) return (int)((const long long*)p)[i];
    return ((const int*)p)[i];
}

// ---------------- CSR build ----------------
__global__ void zero_cnt_kernel() {
    int i = blockIdx.x * blockDim.x + threadIdx.x;
    if (i < NN) g_cnt[i] = 0;
}

__global__ void count_kernel(const void* ei) {
    int e = blockIdx.x * blockDim.x + threadIdx.x;
    if (e < NE) {
        int d = load_idx(ei, (long long)NE + e);
        atomicAdd(&g_cnt[d], 1);
    }
}

// pass 1: per-block (1024) sums of g_cnt
__global__ void scan_reduce_kernel() {
    int i = blockIdx.x * 1024 + threadIdx.x;
    int v = (i < NN) ? g_cnt[i] : 0;
    __shared__ int ws[32];
    int lane = threadIdx.x & 31, wid = threadIdx.x >> 5;
    #pragma unroll
    for (int d = 16; d > 0; d >>= 1) v += __shfl_down_sync(0xffffffffu, v, d);
    if (lane == 0) ws[wid] = v;
    __syncthreads();
    if (wid == 0) {
        int t = ws[lane];
        #pragma unroll
        for (int d = 16; d > 0; d >>= 1) t += __shfl_down_sync(0xffffffffu, t, d);
        if (lane == 0) g_bsum[blockIdx.x] = t;
    }
}

// pass 2: tiny serial scan of block sums
__global__ void scan_bsum_kernel() {
    __shared__ int s[SCAN_B];
    int t = threadIdx.x;
    if (t < SCAN_B) s[t] = g_bsum[t];
    __syncthreads();
    if (t == 0) {
        int acc = 0;
        for (int i = 0; i < SCAN_B; i++) { g_boff[i] = acc; acc += s[i]; }
        g_off[NN] = acc;
    }
}

// pass 3: block-local exclusive scan + block offset; also init g_cur
__global__ void scan_final_kernel() {
    __shared__ int wsum[32];
    int tid = threadIdx.x, lane = tid & 31, wid = tid >> 5;
    int i = blockIdx.x * 1024 + tid;
    int v = (i < NN) ? g_cnt[i] : 0;
    int incl = v;
    #pragma unroll
    for (int d = 1; d < 32; d <<= 1) {
        int t = __shfl_up_sync(0xffffffffu, incl, d);
        if (lane >= d) incl += t;
    }
    if (lane == 31) wsum[wid] = incl;
    __syncthreads();
    if (wid == 0) {
        int wv = wsum[lane];
        int wincl = wv;
        #pragma unroll
        for (int d = 1; d < 32; d <<= 1) {
            int t = __shfl_up_sync(0xffffffffu, wincl, d);
            if (lane >= d) wincl += t;
        }
        wsum[lane] = wincl - wv;
    }
    __syncthreads();
    if (i < NN) {
        int off = g_boff[blockIdx.x] + wsum[wid] + incl - v;
        g_off[i] = off;
        g_cur[i] = off;
    }
}

__global__ void fill_kernel(const void* ei) {
    int e = blockIdx.x * blockDim.x + threadIdx.x;
    if (e < NE) {
        int s = load_idx(ei, e);
        int d = load_idx(ei, (long long)NE + e);
        int pos = atomicAdd(&g_cur[d], 1);
        g_csr[pos] = s;
    }
}

// ---------------- edge aggregation: out[n] = x[n] + sum_{j->n} x[j] ----------------
__global__ void agg_kernel(const float* __restrict__ x, float* __restrict__ out) {
    int w = (blockIdx.x * blockDim.x + threadIdx.x) >> 5;
    int lane = threadIdx.x & 31;
    if (w >= NN) return;
    const float4* xv = (const float4*)x;
    float4 acc = xv[(size_t)w * 32 + lane];
    int s = g_off[w], e = g_off[w + 1];
    for (int i = s; i < e; i++) {
        int nb = __ldg(&g_csr[i]);
        float4 v = __ldg(&xv[(size_t)nb * 32 + lane]);
        acc.x += v.x; acc.y += v.y; acc.z += v.z; acc.w += v.w;
    }
    ((float4*)out)[(size_t)w * 32 + lane] = acc;
}

// ---------------- tf32 tensor-core GEMM: C = act( pre(A) @ W + bias ) ----------------
__device__ __forceinline__ unsigned f2tf(float x) {
    unsigned u;
    asm("cvt.rna.tf32.f32 %0, %1;" : "=r"(u) : "f"(x));
    return u;
}

__device__ __forceinline__ void mma_tf32(float* c, const unsigned* a, const unsigned* b) {
    asm volatile(
        "mma.sync.aligned.m16n8k8.row.col.f32.tf32.tf32.f32 "
        "{%0,%1,%2,%3}, {%4,%5,%6,%7}, {%8,%9}, {%0,%1,%2,%3};"
        : "+f"(c[0]), "+f"(c[1]), "+f"(c[2]), "+f"(c[3])
        : "r"(a[0]), "r"(a[1]), "r"(a[2]), "r"(a[3]), "r"(b[0]), "r"(b[1]));
}

template <bool PRE_BN, bool OUT_RELU>
__global__ __launch_bounds__(256) void gemm_tc_kernel(
    const float* __restrict__ A, const float* __restrict__ W,
    const float* __restrict__ bias,
    const float* __restrict__ scale, const float* __restrict__ shift,
    float* __restrict__ C, int M) {
    extern __shared__ float smem[];
    unsigned* As = (unsigned*)smem;                 // 128 x LDT (row-major, tf32 bits)
    unsigned* Bs = (unsigned*)(smem + 128 * LDT);   // 128 x LDT (n-major: Bs[n*LDT+k])
    int tid = threadIdx.x;
    int r0 = blockIdx.x * 128;

    // W (row-major k x n) -> Bs transposed + cvt
    #pragma unroll
    for (int i = 0; i < 16; i++) {
        int f4 = tid + i * 256;
        int k = f4 >> 5, n4 = f4 & 31;
        float4 w = ((const float4*)W)[f4];
        Bs[(n4 * 4 + 0) * LDT + k] = f2tf(w.x);
        Bs[(n4 * 4 + 1) * LDT + k] = f2tf(w.y);
        Bs[(n4 * 4 + 2) * LDT + k] = f2tf(w.z);
        Bs[(n4 * 4 + 3) * LDT + k] = f2tf(w.w);
    }
    // A tile -> As (+optional fused BN affine + relu) + cvt
    #pragma unroll
    for (int i = 0; i < 16; i++) {
        int f4 = tid + i * 256;
        int row = f4 >> 5, c4 = f4 & 31;
        float4 v = make_float4(0.f, 0.f, 0.f, 0.f);
        if (r0 + row < M)
            v = ((const float4*)(A + (size_t)(r0 + row) * 128))[c4];
        if (PRE_BN) {
            int c = c4 * 4;
            v.x = fmaxf(v.x * __ldg(&scale[c + 0]) + __ldg(&shift[c + 0]), 0.f);
            v.y = fmaxf(v.y * __ldg(&scale[c + 1]) + __ldg(&shift[c + 1]), 0.f);
            v.z = fmaxf(v.z * __ldg(&scale[c + 2]) + __ldg(&shift[c + 2]), 0.f);
            v.w = fmaxf(v.w * __ldg(&scale[c + 3]) + __ldg(&shift[c + 3]), 0.f);
        }
        uint4 u = make_uint4(f2tf(v.x), f2tf(v.y), f2tf(v.z), f2tf(v.w));
        *(uint4*)&As[row * LDT + c4 * 4] = u;
    }
    __syncthreads();

    int wid = tid >> 5, lane = tid & 31;
    int wm = wid >> 1, wn = wid & 1;     // 4 (M) x 2 (N) warps
    int gid = lane >> 2, qid = lane & 3;

    float c[2][8][4];
    #pragma unroll
    for (int mi = 0; mi < 2; mi++)
        #pragma unroll
        for (int ni = 0; ni < 8; ni++)
            #pragma unroll
            for (int j = 0; j < 4; j++) c[mi][ni][j] = 0.f;

    #pragma unroll
    for (int kk = 0; kk < 16; kk++) {
        int k0 = kk * 8;
        unsigned a[2][4];
        #pragma unroll
        for (int mi = 0; mi < 2; mi++) {
            int r = wm * 32 + mi * 16 + gid;
            a[mi][0] = As[r * LDT + k0 + qid];
            a[mi][1] = As[(r + 8) * LDT + k0 + qid];
            a[mi][2] = As[r * LDT + k0 + qid + 4];
            a[mi][3] = As[(r + 8) * LDT + k0 + qid + 4];
        }
        unsigned b[8][2];
        #pragma unroll
        for (int ni = 0; ni < 8; ni++) {
            int n = wn * 64 + ni * 8 + gid;
            b[ni][0] = Bs[n * LDT + k0 + qid];
            b[ni][1] = Bs[n * LDT + k0 + qid + 4];
        }
        #pragma unroll
        for (int mi = 0; mi < 2; mi++)
            #pragma unroll
            for (int ni = 0; ni < 8; ni++)
                mma_tf32(c[mi][ni], a[mi], b[ni]);
    }

    // epilogue: bias (+relu), float2 stores
    #pragma unroll
    for (int ni = 0; ni < 8; ni++) {
        int col = wn * 64 + ni * 8 + 2 * qid;
        float b0 = __ldg(&bias[col]);
        float b1 = __ldg(&bias[col + 1]);
        #pragma unroll
        for (int mi = 0; mi < 2; mi++) {
            int r = r0 + wm * 32 + mi * 16 + gid;
            if (r < M) {
                float o0 = c[mi][ni][0] + b0;
                float o1 = c[mi][ni][1] + b1;
                if (OUT_RELU) { o0 = fmaxf(o0, 0.f); o1 = fmaxf(o1, 0.f); }
                *(float2*)(C + (size_t)r * 128 + col) = make_float2(o0, o1);
            }
            if (r + 8 < M) {
                float o2 = c[mi][ni][2] + b0;
                float o3 = c[mi][ni][3] + b1;
                if (OUT_RELU) { o2 = fmaxf(o2, 0.f); o3 = fmaxf(o3, 0.f); }
                *(float2*)(C + (size_t)(r + 8) * 128 + col) = make_float2(o2, o3);
            }
        }
    }
}

// ---------------- BN column statistics (deterministic tree) ----------------
__global__ void colstats_kernel(const float* __restrict__ h) {
    int c = threadIdx.x;
    int b = blockIdx.x;
    int r0 = b * 400;
    float s = 0.f, q = 0.f;
    for (int r = r0; r < r0 + 400; r += 4) {
        float v0 = h[(size_t)(r + 0) * 128 + c];
        float v1 = h[(size_t)(r + 1) * 128 + c];
        float v2 = h[(size_t)(r + 2) * 128 + c];
        float v3 = h[(size_t)(r + 3) * 128 + c];
        s += v0 + v1 + v2 + v3;
        q += v0 * v0 + v1 * v1 + v2 * v2 + v3 * v3;
    }
    g_psum[b * 128 + c] = s;
    g_psq[b * 128 + c] = q;
}

__global__ void bnfinalize_kernel(const float* __restrict__ gamma,
                                  const float* __restrict__ beta) {
    int c = threadIdx.x;
    float s = 0.f, q = 0.f;
    for (int b = 0; b < 250; b++) {
        s += g_psum[b * 128 + c];
        q += g_psq[b * 128 + c];
    }
    float mu = s / (float)NN;
    float var = q / (float)NN - mu * mu;
    float sc = gamma[c] * rsqrtf(var + BN_EPS);
    g_scale[c] = sc;
    g_shift[c] = beta[c] - mu * sc;
}

// ---------------- pooling (sorted batch -> segmented reduction) + head ----------------
__device__ __forceinline__ int lower_bound_batch(const void* batch, int key) {
    int lo = 0, hi = NN;
    while (lo < hi) {
        int mid = (lo + hi) >> 1;
        int v = load_idx(batch, mid);
        if (v < key) lo = mid + 1; else hi = mid;
    }
    return lo;
}

__global__ void pool_kernel(const float* __restrict__ x, const void* batch) {
    __shared__ int seg[2];
    int g = blockIdx.x;
    int c = threadIdx.x;
    if (c == 0) seg[0] = lower_bound_batch(batch, g);
    if (c == 1) seg[1] = lower_bound_batch(batch, g + 1);
    __syncthreads();
    float acc = 0.f;
    for (int r = seg[0]; r < seg[1]; r++)
        acc += x[(size_t)r * 128 + c];
    g_pooled[g * 128 + c] = acc;
}

__global__ void head_kernel(const float* __restrict__ W1,
                            const float* __restrict__ b1,
                            const float* __restrict__ W2,
                            const float* __restrict__ b2,
                            float* __restrict__ out) {
    __shared__ float pr[128];
    __shared__ float h1[128];
    int g = blockIdx.x;
    int t = threadIdx.x;
    pr[t] = g_pooled[g * 128 + t];
    __syncthreads();
    float s = b1[t];
    #pragma unroll 8
    for (int k = 0; k < 128; k++) s += pr[k] * W1[k * 128 + t];
    h1[t] = fmaxf(s, 0.f);
    __syncthreads();
    if (t < NC) {
        float o = b2[t];
        #pragma unroll 8
        for (int k = 0; k < 128; k++) o += h1[k] * W2[k * NC + t];
        out[g * NC + t] = o;
    }
}

// ---------------- launcher ----------------
extern "C" void kernel_launch(void* const* d_in, const int* in_sizes, int n_in,
                              void* d_out, int out_size) {
    const float* x       = (const float*)d_in[0];
    const void*  ei      = d_in[1];
    const void*  batch   = d_in[2];
    const float* conv_W1 = (const float*)d_in[3];
    const float* conv_b1 = (const float*)d_in[4];
    const float* conv_g  = (const float*)d_in[5];
    const float* conv_bt = (const float*)d_in[6];
    const float* conv_W2 = (const float*)d_in[7];
    const float* conv_b2 = (const float*)d_in[8];
    const float* head_W1 = (const float*)d_in[9];
    const float* head_b1 = (const float*)d_in[10];
    const float* head_W2 = (const float*)d_in[11];
    const float* head_b2 = (const float*)d_in[12];
    float* out = (float*)d_out;

    float *P, *Q, *scale, *shift;
    cudaGetSymbolAddress((void**)&P, g_P);
    cudaGetSymbolAddress((void**)&Q, g_Q);
    cudaGetSymbolAddress((void**)&scale, g_scale);
    cudaGetSymbolAddress((void**)&shift, g_shift);

    const int SMEM = 2 * 128 * LDT * 4;  // 135168 B (< 227KB sm_100a opt-in ceiling)
    cudaFuncSetAttribute(gemm_tc_kernel<false, false>,
                         cudaFuncAttributeMaxDynamicSharedMemorySize, SMEM);
    cudaFuncSetAttribute(gemm_tc_kernel<true, true>,
                         cudaFuncAttributeMaxDynamicSharedMemorySize, SMEM);

    // index-width detection
    detect_kernel<<<1, 1>>>((const unsigned*)ei);

    // CSR build (reused by all 5 layers)
    zero_cnt_kernel<<<(NN + 255) / 256, 256>>>();
    count_kernel<<<NE / 256, 256>>>(ei);
    scan_reduce_kernel<<<SCAN_B, 1024>>>();
    scan_bsum_kernel<<<1, 128>>>();
    scan_final_kernel<<<SCAN_B, 1024>>>();
    fill_kernel<<<NE / 256, 256>>>(ei);

    const int GEMM_GRID = (NN + 127) / 128;
    const float* xin = x;
    for (int l = 0; l < NL; l++) {
        agg_kernel<<<(NN * 32 + 255) / 256, 256>>>(xin, Q);
        gemm_tc_kernel<false, false><<<GEMM_GRID, 256, SMEM>>>(
            Q, conv_W1 + (size_t)l * FD * FD, conv_b1 + l * FD,
            nullptr, nullptr, Q, NN);
        colstats_kernel<<<250, 128>>>(Q);
        bnfinalize_kernel<<<1, 128>>>(conv_g + l * FD, conv_bt + l * FD);
        gemm_tc_kernel<true, true><<<GEMM_GRID, 256, SMEM>>>(
            Q, conv_W2 + (size_t)l * FD * FD, conv_b2 + l * FD,
            scale, shift, P, NN);
        xin = P;
    }

    pool_kernel<<<NG, 128>>>(P, batch);
    head_kernel<<<NG, 128>>>(head_W1, head_b1, head_W2, head_b2, out);
}

// round 6
// speedup vs baseline: 1.4238x; 1.0185x over previous
#include <cuda_runtime.h>
#include <cuda_bf16.h>
#include <cstdint>

#define NN 100000
#define NE 1600000
#define FD 128
#define NG 512
#define NC 10
#define NL 5
#define BN_EPS 1e-5f
#define SCAN_B 98                  // ceil(NN/1024)
#define LDT 132                    // padded smem stride (words)
#define GB1 ((NN + 63) / 64)       // 1563 GEMM blocks (M-tile 64)

// ---------------- scratch (device globals; no allocs allowed) ----------------
__device__ float g_P[NN * FD];
__device__ float g_Q[NN * FD];
__device__ float g_pooled[NG * FD];
__device__ float g_psum[GB1 * FD];
__device__ float g_psq[GB1 * FD];
__device__ float g_scale[FD];
__device__ float g_shift[FD];
__device__ int   g_cnt[NN];
__device__ int   g_off[NN + 1];
__device__ int   g_cur[NN];
__device__ int   g_csr[NE];
__device__ int   g_bsum[SCAN_B];
__device__ int   g_boff[SCAN_B];
__device__ int   g_is64;

// ---------------- index-width detection ----------------
__global__ void detect_kernel(const unsigned* ei_words) {
    if (threadIdx.x == 0 && blockIdx.x == 0) {
        int is64 = 1;
        for (int i = 1; i < 64; i++) {
            if (ei_words[2 * i + 1] != 0u) { is64 = 0; break; }
        }
        g_is64 = is64;
    }
}

__device__ __forceinline__ int load_idx(const void* p, long long i) {
    if (g_is64) return (int)((const long long*)p)[i];
    return ((const int*)p)[i];
}

// ---------------- CSR build ----------------
__global__ void zero_cnt_kernel() {
    int i = blockIdx.x * blockDim.x + threadIdx.x;
    if (i < NN) g_cnt[i] = 0;
}

__global__ void count_kernel(const void* ei) {
    int e = blockIdx.x * blockDim.x + threadIdx.x;
    if (e < NE) {
        int d = load_idx(ei, (long long)NE + e);
        atomicAdd(&g_cnt[d], 1);
    }
}

__global__ void scan_reduce_kernel() {
    int i = blockIdx.x * 1024 + threadIdx.x;
    int v = (i < NN) ? g_cnt[i] : 0;
    __shared__ int ws[32];
    int lane = threadIdx.x & 31, wid = threadIdx.x >> 5;
    #pragma unroll
    for (int d = 16; d > 0; d >>= 1) v += __shfl_down_sync(0xffffffffu, v, d);
    if (lane == 0) ws[wid] = v;
    __syncthreads();
    if (wid == 0) {
        int t = ws[lane];
        #pragma unroll
        for (int d = 16; d > 0; d >>= 1) t += __shfl_down_sync(0xffffffffu, t, d);
        if (lane == 0) g_bsum[blockIdx.x] = t;
    }
}

__global__ void scan_bsum_kernel() {
    __shared__ int s[SCAN_B];
    int t = threadIdx.x;
    if (t < SCAN_B) s[t] = g_bsum[t];
    __syncthreads();
    if (t == 0) {
        int acc = 0;
        for (int i = 0; i < SCAN_B; i++) { g_boff[i] = acc; acc += s[i]; }
        g_off[NN] = acc;
    }
}

__global__ void scan_final_kernel() {
    __shared__ int wsum[32];
    int tid = threadIdx.x, lane = tid & 31, wid = tid >> 5;
    int i = blockIdx.x * 1024 + tid;
    int v = (i < NN) ? g_cnt[i] : 0;
    int incl = v;
    #pragma unroll
    for (int d = 1; d < 32; d <<= 1) {
        int t = __shfl_up_sync(0xffffffffu, incl, d);
        if (lane >= d) incl += t;
    }
    if (lane == 31) wsum[wid] = incl;
    __syncthreads();
    if (wid == 0) {
        int wv = wsum[lane];
        int wincl = wv;
        #pragma unroll
        for (int d = 1; d < 32; d <<= 1) {
            int t = __shfl_up_sync(0xffffffffu, wincl, d);
            if (lane >= d) wincl += t;
        }
        wsum[lane] = wincl - wv;
    }
    __syncthreads();
    if (i < NN) {
        int off = g_boff[blockIdx.x] + wsum[wid] + incl - v;
        g_off[i] = off;
        g_cur[i] = off;
    }
}

__global__ void fill_kernel(const void* ei) {
    int e = blockIdx.x * blockDim.x + threadIdx.x;
    if (e < NE) {
        int s = load_idx(ei, e);
        int d = load_idx(ei, (long long)NE + e);
        int pos = atomicAdd(&g_cur[d], 1);
        g_csr[pos] = s;
    }
}

// ---------------- tf32 helpers ----------------
__device__ __forceinline__ unsigned f2tf(float x) {
    unsigned u;
    asm("cvt.rna.tf32.f32 %0, %1;" : "=r"(u) : "f"(x));
    return u;
}

__device__ __forceinline__ void mma_tf32(float* c, const unsigned* a, const unsigned* b) {
    asm volatile(
        "mma.sync.aligned.m16n8k8.row.col.f32.tf32.tf32.f32 "
        "{%0,%1,%2,%3}, {%4,%5,%6,%7}, {%8,%9}, {%0,%1,%2,%3};"
        : "+f"(c[0]), "+f"(c[1]), "+f"(c[2]), "+f"(c[3])
        : "r"(a[0]), "r"(a[1]), "r"(a[2]), "r"(a[3]), "r"(b[0]), "r"(b[1]));
}

// ---------------- fused tf32 GEMM, M-tile 64 ----------------
// GATHER:  A-tile rows = A[row] + sum_{j->row} A[csr[j]]  (GIN aggregation)
// PRE_BN:  per-column affine + relu on A rows (fused batchnorm)
// OUT_RELU: relu on output
// STATS:   per-block column sum/sumsq partials of the output
// NOTE: no minBlocksPerMultiprocessor contract (bisect vs R4/R5 failures);
//       2 CTA/SM still fits by smem (2 x 101376 B < 227 KB) if regs allow.
template <bool GATHER, bool PRE_BN, bool OUT_RELU, bool STATS>
__global__ __launch_bounds__(256) void gemm64_kernel(
    const float* __restrict__ A, const float* __restrict__ W,
    const float* __restrict__ bias,
    const float* __restrict__ scale, const float* __restrict__ shift,
    float* __restrict__ C, int M) {
    extern __shared__ float smemf[];
    unsigned* As = (unsigned*)smemf;          // 64 x LDT
    unsigned* Bs = As + 64 * LDT;             // 128 x LDT (n-major: Bs[n*LDT+k])
    int tid = threadIdx.x;
    int r0 = blockIdx.x * 64;

    // --- W (row-major k x n) -> Bs[n][k], transpose via k-strided global reads,
    //     conflict-free uint4 smem stores (bank = 4n+k0, distinct per phase) ---
    #pragma unroll
    for (int i = 0; i < 16; i++) {
        int task = tid + i * 256;        // 0..4095
        int n = task & 127, k0 = (task >> 7) * 4;
        float w0 = __ldg(&W[(k0 + 0) * 128 + n]);
        float w1 = __ldg(&W[(k0 + 1) * 128 + n]);
        float w2 = __ldg(&W[(k0 + 2) * 128 + n]);
        float w3 = __ldg(&W[(k0 + 3) * 128 + n]);
        uint4 u = make_uint4(f2tf(w0), f2tf(w1), f2tf(w2), f2tf(w3));
        *(uint4*)&Bs[n * LDT + k0] = u;
    }

    if (GATHER) {
        // warp w handles rows w*8 .. w*8+7: row = A[gr] + sum of neighbor rows
        int w = tid >> 5, lane = tid & 31;
        const float4* av = (const float4*)A;
        for (int rr = 0; rr < 8; rr++) {
            int rl = w * 8 + rr;
            int gr = r0 + rl;
            float4 acc = make_float4(0.f, 0.f, 0.f, 0.f);
            if (gr < M) {
                acc = av[(size_t)gr * 32 + lane];
                int s = g_off[gr], e = g_off[gr + 1];
                for (int i = s; i < e; i++) {
                    int nb = __ldg(&g_csr[i]);
                    float4 v = __ldg(&av[(size_t)nb * 32 + lane]);
                    acc.x += v.x; acc.y += v.y; acc.z += v.z; acc.w += v.w;
                }
            }
            uint4 u = make_uint4(f2tf(acc.x), f2tf(acc.y), f2tf(acc.z), f2tf(acc.w));
            *(uint4*)&As[rl * LDT + lane * 4] = u;
        }
    } else {
        #pragma unroll
        for (int i = 0; i < 8; i++) {
            int f4 = tid + i * 256;      // 0..2047
            int row = f4 >> 5, c4 = f4 & 31;
            float4 v = make_float4(0.f, 0.f, 0.f, 0.f);
            if (r0 + row < M)
                v = ((const float4*)(A + (size_t)(r0 + row) * 128))[c4];
            if (PRE_BN) {
                int c = c4 * 4;
                v.x = fmaxf(v.x * __ldg(&scale[c + 0]) + __ldg(&shift[c + 0]), 0.f);
                v.y = fmaxf(v.y * __ldg(&scale[c + 1]) + __ldg(&shift[c + 1]), 0.f);
                v.z = fmaxf(v.z * __ldg(&scale[c + 2]) + __ldg(&shift[c + 2]), 0.f);
                v.w = fmaxf(v.w * __ldg(&scale[c + 3]) + __ldg(&shift[c + 3]), 0.f);
            }
            uint4 u = make_uint4(f2tf(v.x), f2tf(v.y), f2tf(v.z), f2tf(v.w));
            *(uint4*)&As[row * LDT + c4 * 4] = u;
        }
    }
    __syncthreads();

    int wid = tid >> 5, lane = tid & 31;
    int wm = wid >> 2, wn = wid & 3;     // 2 (M) x 4 (N) warps; warp tile 32x32
    int gid = lane >> 2, qid = lane & 3;

    float c[2][4][4];
    #pragma unroll
    for (int mi = 0; mi < 2; mi++)
        #pragma unroll
        for (int ni = 0; ni < 4; ni++)
            #pragma unroll
            for (int j = 0; j < 4; j++) c[mi][ni][j] = 0.f;

    #pragma unroll
    for (int kk = 0; kk < 16; kk++) {
        int k0 = kk * 8;
        unsigned a[2][4];
        #pragma unroll
        for (int mi = 0; mi < 2; mi++) {
            int r = wm * 32 + mi * 16 + gid;
            a[mi][0] = As[r * LDT + k0 + qid];
            a[mi][1] = As[(r + 8) * LDT + k0 + qid];
            a[mi][2] = As[r * LDT + k0 + qid + 4];
            a[mi][3] = As[(r + 8) * LDT + k0 + qid + 4];
        }
        unsigned b[4][2];
        #pragma unroll
        for (int ni = 0; ni < 4; ni++) {
            int n = wn * 32 + ni * 8 + gid;
            b[ni][0] = Bs[n * LDT + k0 + qid];
            b[ni][1] = Bs[n * LDT + k0 + qid + 4];
        }
        #pragma unroll
        for (int mi = 0; mi < 2; mi++)
            #pragma unroll
            for (int ni = 0; ni < 4; ni++)
                mma_tf32(c[mi][ni], a[mi], b[ni]);
    }

    // ---- epilogue: bias (+relu), stores; optional column-stat partials ----
    float sarr[8], qarr[8];
    if (STATS) {
        #pragma unroll
        for (int t = 0; t < 8; t++) { sarr[t] = 0.f; qarr[t] = 0.f; }
    }
    #pragma unroll
    for (int ni = 0; ni < 4; ni++) {
        int col = wn * 32 + ni * 8 + 2 * qid;
        float b0 = __ldg(&bias[col]);
        float b1 = __ldg(&bias[col + 1]);
        #pragma unroll
        for (int mi = 0; mi < 2; mi++) {
            int gr = r0 + wm * 32 + mi * 16 + gid;
            float o0 = c[mi][ni][0] + b0;
            float o1 = c[mi][ni][1] + b1;
            float o2 = c[mi][ni][2] + b0;
            float o3 = c[mi][ni][3] + b1;
            if (OUT_RELU) {
                o0 = fmaxf(o0, 0.f); o1 = fmaxf(o1, 0.f);
                o2 = fmaxf(o2, 0.f); o3 = fmaxf(o3, 0.f);
            }
            if (gr < M) {
                *(float2*)(C + (size_t)gr * 128 + col) = make_float2(o0, o1);
                if (STATS) {
                    sarr[ni * 2 + 0] += o0; qarr[ni * 2 + 0] += o0 * o0;
                    sarr[ni * 2 + 1] += o1; qarr[ni * 2 + 1] += o1 * o1;
                }
            }
            if (gr + 8 < M) {
                *(float2*)(C + (size_t)(gr + 8) * 128 + col) = make_float2(o2, o3);
                if (STATS) {
                    sarr[ni * 2 + 0] += o2; qarr[ni * 2 + 0] += o2 * o2;
                    sarr[ni * 2 + 1] += o3; qarr[ni * 2 + 1] += o3 * o3;
                }
            }
        }
    }

    if (STATS) {
        // reduce over gid lanes (same qid): butterfly masks 4,8,16 (deterministic)
        #pragma unroll
        for (int t = 0; t < 8; t++) {
            #pragma unroll
            for (int m = 4; m <= 16; m <<= 1) {
                sarr[t] += __shfl_xor_sync(0xffffffffu, sarr[t], m);
                qarr[t] += __shfl_xor_sync(0xffffffffu, qarr[t], m);
            }
        }
        __syncthreads();                 // done reading As/Bs; reuse as scratch
        float* sS = smemf;               // [2][128]
        float* sQ = smemf + 256;         // [2][128]
        if (gid == 0) {
            #pragma unroll
            for (int t = 0; t < 8; t++) {
                int col = wn * 32 + (t >> 1) * 8 + 2 * qid + (t & 1);
                sS[wm * 128 + col] = sarr[t];
                sQ[wm * 128 + col] = qarr[t];
            }
        }
        __syncthreads();
        if (tid < 128) {
            g_psum[blockIdx.x * 128 + tid] = sS[tid] + sS[128 + tid];
            g_psq[blockIdx.x * 128 + tid] = sQ[tid] + sQ[128 + tid];
        }
    }
}

// ---------------- BN finalize over GB1 partials (deterministic) ----------------
__global__ void bnfinalize_kernel(const float* __restrict__ gamma,
                                  const float* __restrict__ beta) {
    __shared__ float ss[8][128];
    __shared__ float qq[8][128];
    int c = threadIdx.x & 127;
    int chunk = threadIdx.x >> 7;    // 0..7
    float s = 0.f, q = 0.f;
    for (int i = chunk; i < GB1; i += 8) {
        s += g_psum[i * 128 + c];
        q += g_psq[i * 128 + c];
    }
    ss[chunk][c] = s;
    qq[chunk][c] = q;
    __syncthreads();
    if (threadIdx.x < 128) {
        float S = 0.f, Qv = 0.f;
        #pragma unroll
        for (int k = 0; k < 8; k++) { S += ss[k][c]; Qv += qq[k][c]; }
        float mu = S / (float)NN;
        float var = Qv / (float)NN - mu * mu;
        float sc = gamma[c] * rsqrtf(var + BN_EPS);
        g_scale[c] = sc;
        g_shift[c] = beta[c] - mu * sc;
    }
}

// ---------------- pooling (sorted batch -> segmented reduction) + head ----------------
__device__ __forceinline__ int lower_bound_batch(const void* batch, int key) {
    int lo = 0, hi = NN;
    while (lo < hi) {
        int mid = (lo + hi) >> 1;
        int v = load_idx(batch, mid);
        if (v < key) lo = mid + 1; else hi = mid;
    }
    return lo;
}

__global__ void pool_kernel(const float* __restrict__ x, const void* batch) {
    __shared__ int seg[2];
    int g = blockIdx.x;
    int c = threadIdx.x;
    if (c == 0) seg[0] = lower_bound_batch(batch, g);
    if (c == 1) seg[1] = lower_bound_batch(batch, g + 1);
    __syncthreads();
    float acc = 0.f;
    for (int r = seg[0]; r < seg[1]; r++)
        acc += x[(size_t)r * 128 + c];
    g_pooled[g * 128 + c] = acc;
}

__global__ void head_kernel(const float* __restrict__ W1,
                            const float* __restrict__ b1,
                            const float* __restrict__ W2,
                            const float* __restrict__ b2,
                            float* __restrict__ out) {
    __shared__ float pr[128];
    __shared__ float h1[128];
    int g = blockIdx.x;
    int t = threadIdx.x;
    pr[t] = g_pooled[g * 128 + t];
    __syncthreads();
    float s = b1[t];
    #pragma unroll 8
    for (int k = 0; k < 128; k++) s += pr[k] * W1[k * 128 + t];
    h1[t] = fmaxf(s, 0.f);
    __syncthreads();
    if (t < NC) {
        float o = b2[t];
        #pragma unroll 8
        for (int k = 0; k < 128; k++) o += h1[k] * W2[k * NC + t];
        out[g * NC + t] = o;
    }
}

// ---------------- launcher ----------------
extern "C" void kernel_launch(void* const* d_in, const int* in_sizes, int n_in,
                              void* d_out, int out_size) {
    const float* x       = (const float*)d_in[0];
    const void*  ei      = d_in[1];
    const void*  batch   = d_in[2];
    const float* conv_W1 = (const float*)d_in[3];
    const float* conv_b1 = (const float*)d_in[4];
    const float* conv_g  = (const float*)d_in[5];
    const float* conv_bt = (const float*)d_in[6];
    const float* conv_W2 = (const float*)d_in[7];
    const float* conv_b2 = (const float*)d_in[8];
    const float* head_W1 = (const float*)d_in[9];
    const float* head_b1 = (const float*)d_in[10];
    const float* head_W2 = (const float*)d_in[11];
    const float* head_b2 = (const float*)d_in[12];
    float* out = (float*)d_out;

    float *P, *Q, *scale, *shift;
    cudaGetSymbolAddress((void**)&P, g_P);
    cudaGetSymbolAddress((void**)&Q, g_Q);
    cudaGetSymbolAddress((void**)&scale, g_scale);
    cudaGetSymbolAddress((void**)&shift, g_shift);

    const int SMEM = (64 + 128) * LDT * 4;   // 101376 B
    cudaFuncSetAttribute(gemm64_kernel<true, false, false, true>,
                         cudaFuncAttributeMaxDynamicSharedMemorySize, SMEM);
    cudaFuncSetAttribute(gemm64_kernel<false, true, true, false>,
                         cudaFuncAttributeMaxDynamicSharedMemorySize, SMEM);

    // index-width detection
    detect_kernel<<<1, 1>>>((const unsigned*)ei);

    // CSR build (reused by all 5 layers)
    zero_cnt_kernel<<<(NN + 255) / 256, 256>>>();
    count_kernel<<<NE / 256, 256>>>(ei);
    scan_reduce_kernel<<<SCAN_B, 1024>>>();
    scan_bsum_kernel<<<1, 128>>>();
    scan_final_kernel<<<SCAN_B, 1024>>>();
    fill_kernel<<<NE / 256, 256>>>(ei);

    const float* xin = x;
    for (int l = 0; l < NL; l++) {
        // Q = (xin + sum_neighbors xin) @ W1 + b1, with fused column stats
        gemm64_kernel<true, false, false, true><<<GB1, 256, SMEM>>>(
            xin, conv_W1 + (size_t)l * FD * FD, conv_b1 + l * FD,
            nullptr, nullptr, Q, NN);
        bnfinalize_kernel<<<1, 1024>>>(conv_g + l * FD, conv_bt + l * FD);
        // P = relu( relu(BN(Q)) @ W2 + b2 )
        gemm64_kernel<false, true, true, false><<<GB1, 256, SMEM>>>(
            Q, conv_W2 + (size_t)l * FD * FD, conv_b2 + l * FD,
            scale, shift, P, NN);
        xin = P;
    }

    pool_kernel<<<NG, 128>>>(P, batch);
    head_kernel<<<NG, 128>>>(head_W1, head_b1, head_W2, head_b2, out);
}

// round 8
// speedup vs baseline: 1.8119x; 1.2726x over previous
#include <cuda_runtime.h>
#include <cuda_bf16.h>
#include <cstdint>

#define NN 100000
#define NE 1600000
#define FD 128
#define NG 512
#define NC 10
#define NL 5
#define BN_EPS 1e-5f
#define SCAN_B 98                  // ceil(NN/1024)
#define LDT 132                    // padded smem stride (words)
#define GB1 ((NN + 63) / 64)       // 1563 GEMM blocks (M-tile 64)

// ---------------- scratch (device globals; no allocs allowed) ----------------
__device__ float g_P[NN * FD];
__device__ float g_Q[NN * FD];
__device__ float g_R[NN * FD];
__device__ float g_pooled[NG * FD];
__device__ float g_psum[GB1 * FD];
__device__ float g_psq[GB1 * FD];
__device__ float g_scale[FD];
__device__ float g_shift[FD];
__device__ int   g_cnt[NN];
__device__ int   g_off[NN + 1];
__device__ int   g_cur[NN];
__device__ int   g_csr[NE];
__device__ int   g_bsum[SCAN_B];
__device__ int   g_boff[SCAN_B];
__device__ int   g_is64;

// ---------------- index-width detection ----------------
__global__ void detect_kernel(const unsigned* ei_words) {
    if (threadIdx.x == 0 && blockIdx.x == 0) {
        int is64 = 1;
        for (int i = 1; i < 64; i++) {
            if (ei_words[2 * i + 1] != 0u) { is64 = 0; break; }
        }
        g_is64 = is64;
    }
}

__device__ __forceinline__ int load_idx(const void* p, long long i) {
    if (g_is64) return (int)((const long long*)p)[i];
    return ((const int*)p)[i];
}

// ---------------- CSR build ----------------
__global__ void zero_cnt_kernel() {
    int i = blockIdx.x * blockDim.x + threadIdx.x;
    if (i < NN) g_cnt[i] = 0;
}

__global__ void count_kernel(const void* ei) {
    int e = blockIdx.x * blockDim.x + threadIdx.x;
    if (e < NE) {
        int d = load_idx(ei, (long long)NE + e);
        atomicAdd(&g_cnt[d], 1);
    }
}

__global__ void scan_reduce_kernel() {
    int i = blockIdx.x * 1024 + threadIdx.x;
    int v = (i < NN) ? g_cnt[i] : 0;
    __shared__ int ws[32];
    int lane = threadIdx.x & 31, wid = threadIdx.x >> 5;
    #pragma unroll
    for (int d = 16; d > 0; d >>= 1) v += __shfl_down_sync(0xffffffffu, v, d);
    if (lane == 0) ws[wid] = v;
    __syncthreads();
    if (wid == 0) {
        int t = ws[lane];
        #pragma unroll
        for (int d = 16; d > 0; d >>= 1) t += __shfl_down_sync(0xffffffffu, t, d);
        if (lane == 0) g_bsum[blockIdx.x] = t;
    }
}

__global__ void scan_bsum_kernel() {
    __shared__ int s[SCAN_B];
    int t = threadIdx.x;
    if (t < SCAN_B) s[t] = g_bsum[t];
    __syncthreads();
    if (t == 0) {
        int acc = 0;
        for (int i = 0; i < SCAN_B; i++) { g_boff[i] = acc; acc += s[i]; }
        g_off[NN] = acc;
    }
}

__global__ void scan_final_kernel() {
    __shared__ int wsum[32];
    int tid = threadIdx.x, lane = tid & 31, wid = tid >> 5;
    int i = blockIdx.x * 1024 + tid;
    int v = (i < NN) ? g_cnt[i] : 0;
    int incl = v;
    #pragma unroll
    for (int d = 1; d < 32; d <<= 1) {
        int t = __shfl_up_sync(0xffffffffu, incl, d);
        if (lane >= d) incl += t;
    }
    if (lane == 31) wsum[wid] = incl;
    __syncthreads();
    if (wid == 0) {
        int wv = wsum[lane];
        int wincl = wv;
        #pragma unroll
        for (int d = 1; d < 32; d <<= 1) {
            int t = __shfl_up_sync(0xffffffffu, wincl, d);
            if (lane >= d) wincl += t;
        }
        wsum[lane] = wincl - wv;
    }
    __syncthreads();
    if (i < NN) {
        int off = g_boff[blockIdx.x] + wsum[wid] + incl - v;
        g_off[i] = off;
        g_cur[i] = off;
    }
}

__global__ void fill_kernel(const void* ei) {
    int e = blockIdx.x * blockDim.x + threadIdx.x;
    if (e < NE) {
        int s = load_idx(ei, e);
        int d = load_idx(ei, (long long)NE + e);
        int pos = atomicAdd(&g_cur[d], 1);
        g_csr[pos] = s;
    }
}

// ---------------- edge aggregation: out[n] = x[n] + sum_{j->n} x[j] ----------------
// 1 warp per node (100k warps in flight); neighbor loop unrolled x4 for MLP.
__global__ __launch_bounds__(256) void agg_kernel(const float* __restrict__ x,
                                                  float* __restrict__ out) {
    int w = (blockIdx.x * blockDim.x + threadIdx.x) >> 5;
    int lane = threadIdx.x & 31;
    if (w >= NN) return;
    const float4* xv = (const float4*)x;
    float4 acc = xv[(size_t)w * 32 + lane];
    int s = g_off[w], e = g_off[w + 1];
    int i = s;
    for (; i + 4 <= e; i += 4) {
        int n0 = __ldg(&g_csr[i + 0]);
        int n1 = __ldg(&g_csr[i + 1]);
        int n2 = __ldg(&g_csr[i + 2]);
        int n3 = __ldg(&g_csr[i + 3]);
        float4 v0 = __ldg(&xv[(size_t)n0 * 32 + lane]);
        float4 v1 = __ldg(&xv[(size_t)n1 * 32 + lane]);
        float4 v2 = __ldg(&xv[(size_t)n2 * 32 + lane]);
        float4 v3 = __ldg(&xv[(size_t)n3 * 32 + lane]);
        acc.x += v0.x + v1.x + v2.x + v3.x;
        acc.y += v0.y + v1.y + v2.y + v3.y;
        acc.z += v0.z + v1.z + v2.z + v3.z;
        acc.w += v0.w + v1.w + v2.w + v3.w;
    }
    for (; i < e; i++) {
        int nb = __ldg(&g_csr[i]);
        float4 v = __ldg(&xv[(size_t)nb * 32 + lane]);
        acc.x += v.x; acc.y += v.y; acc.z += v.z; acc.w += v.w;
    }
    ((float4*)out)[(size_t)w * 32 + lane] = acc;
}

// ---------------- tf32 helpers ----------------
__device__ __forceinline__ unsigned f2tf(float x) {
    unsigned u;
    asm("cvt.rna.tf32.f32 %0, %1;" : "=r"(u) : "f"(x));
    return u;
}

__device__ __forceinline__ void mma_tf32(float* c, const unsigned* a, const unsigned* b) {
    asm volatile(
        "mma.sync.aligned.m16n8k8.row.col.f32.tf32.tf32.f32 "
        "{%0,%1,%2,%3}, {%4,%5,%6,%7}, {%8,%9}, {%0,%1,%2,%3};"
        : "+f"(c[0]), "+f"(c[1]), "+f"(c[2]), "+f"(c[3])
        : "r"(a[0]), "r"(a[1]), "r"(a[2]), "r"(a[3]), "r"(b[0]), "r"(b[1]));
}

// ---------------- tf32 GEMM, M-tile 64: C = act( pre(A) @ W + bias ) ----------------
// PRE_BN:  per-column affine + relu on A rows (fused batchnorm)
// OUT_RELU: relu on output
// STATS:   per-block column sum/sumsq partials of the output
template <bool PRE_BN, bool OUT_RELU, bool STATS>
__global__ __launch_bounds__(256) void gemm64_kernel(
    const float* __restrict__ A, const float* __restrict__ W,
    const float* __restrict__ bias,
    const float* __restrict__ scale, const float* __restrict__ shift,
    float* __restrict__ C, int M) {
    extern __shared__ float smemf[];
    unsigned* As = (unsigned*)smemf;          // 64 x LDT
    unsigned* Bs = As + 64 * LDT;             // 128 x LDT (n-major: Bs[n*LDT+k])
    int tid = threadIdx.x;
    int r0 = blockIdx.x * 64;

    // W (row-major k x n) -> Bs[n][k]: transpose via k-strided global reads,
    // conflict-free uint4 smem stores (bank = 4n+k0, distinct per phase)
    #pragma unroll
    for (int i = 0; i < 16; i++) {
        int task = tid + i * 256;        // 0..4095
        int n = task & 127, k0 = (task >> 7) * 4;
        float w0 = __ldg(&W[(k0 + 0) * 128 + n]);
        float w1 = __ldg(&W[(k0 + 1) * 128 + n]);
        float w2 = __ldg(&W[(k0 + 2) * 128 + n]);
        float w3 = __ldg(&W[(k0 + 3) * 128 + n]);
        uint4 u = make_uint4(f2tf(w0), f2tf(w1), f2tf(w2), f2tf(w3));
        *(uint4*)&Bs[n * LDT + k0] = u;
    }
    // A tile -> As (+optional fused BN affine + relu) + cvt
    #pragma unroll
    for (int i = 0; i < 8; i++) {
        int f4 = tid + i * 256;          // 0..2047
        int row = f4 >> 5, c4 = f4 & 31;
        float4 v = make_float4(0.f, 0.f, 0.f, 0.f);
        if (r0 + row < M)
            v = ((const float4*)(A + (size_t)(r0 + row) * 128))[c4];
        if (PRE_BN) {
            int c = c4 * 4;
            v.x = fmaxf(v.x * __ldg(&scale[c + 0]) + __ldg(&shift[c + 0]), 0.f);
            v.y = fmaxf(v.y * __ldg(&scale[c + 1]) + __ldg(&shift[c + 1]), 0.f);
            v.z = fmaxf(v.z * __ldg(&scale[c + 2]) + __ldg(&shift[c + 2]), 0.f);
            v.w = fmaxf(v.w * __ldg(&scale[c + 3]) + __ldg(&shift[c + 3]), 0.f);
        }
        uint4 u = make_uint4(f2tf(v.x), f2tf(v.y), f2tf(v.z), f2tf(v.w));
        *(uint4*)&As[row * LDT + c4 * 4] = u;
    }
    __syncthreads();

    int wid = tid >> 5, lane = tid & 31;
    int wm = wid >> 2, wn = wid & 3;     // 2 (M) x 4 (N) warps; warp tile 32x32
    int gid = lane >> 2, qid = lane & 3;

    float c[2][4][4];
    #pragma unroll
    for (int mi = 0; mi < 2; mi++)
        #pragma unroll
        for (int ni = 0; ni < 4; ni++)
            #pragma unroll
            for (int j = 0; j < 4; j++) c[mi][ni][j] = 0.f;

    #pragma unroll
    for (int kk = 0; kk < 16; kk++) {
        int k0 = kk * 8;
        unsigned a[2][4];
        #pragma unroll
        for (int mi = 0; mi < 2; mi++) {
            int r = wm * 32 + mi * 16 + gid;
            a[mi][0] = As[r * LDT + k0 + qid];
            a[mi][1] = As[(r + 8) * LDT + k0 + qid];
            a[mi][2] = As[r * LDT + k0 + qid + 4];
            a[mi][3] = As[(r + 8) * LDT + k0 + qid + 4];
        }
        unsigned b[4][2];
        #pragma unroll
        for (int ni = 0; ni < 4; ni++) {
            int n = wn * 32 + ni * 8 + gid;
            b[ni][0] = Bs[n * LDT + k0 + qid];
            b[ni][1] = Bs[n * LDT + k0 + qid + 4];
        }
        #pragma unroll
        for (int mi = 0; mi < 2; mi++)
            #pragma unroll
            for (int ni = 0; ni < 4; ni++)
                mma_tf32(c[mi][ni], a[mi], b[ni]);
    }

    // ---- epilogue: bias (+relu), stores; optional column-stat partials ----
    float sarr[8], qarr[8];
    if (STATS) {
        #pragma unroll
        for (int t = 0; t < 8; t++) { sarr[t] = 0.f; qarr[t] = 0.f; }
    }
    #pragma unroll
    for (int ni = 0; ni < 4; ni++) {
        int col = wn * 32 + ni * 8 + 2 * qid;
        float b0 = __ldg(&bias[col]);
        float b1 = __ldg(&bias[col + 1]);
        #pragma unroll
        for (int mi = 0; mi < 2; mi++) {
            int gr = r0 + wm * 32 + mi * 16 + gid;
            float o0 = c[mi][ni][0] + b0;
            float o1 = c[mi][ni][1] + b1;
            float o2 = c[mi][ni][2] + b0;
            float o3 = c[mi][ni][3] + b1;
            if (OUT_RELU) {
                o0 = fmaxf(o0, 0.f); o1 = fmaxf(o1, 0.f);
                o2 = fmaxf(o2, 0.f); o3 = fmaxf(o3, 0.f);
            }
            if (gr < M) {
                *(float2*)(C + (size_t)gr * 128 + col) = make_float2(o0, o1);
                if (STATS) {
                    sarr[ni * 2 + 0] += o0; qarr[ni * 2 + 0] += o0 * o0;
                    sarr[ni * 2 + 1] += o1; qarr[ni * 2 + 1] += o1 * o1;
                }
            }
            if (gr + 8 < M) {
                *(float2*)(C + (size_t)(gr + 8) * 128 + col) = make_float2(o2, o3);
                if (STATS) {
                    sarr[ni * 2 + 0] += o2; qarr[ni * 2 + 0] += o2 * o2;
                    sarr[ni * 2 + 1] += o3; qarr[ni * 2 + 1] += o3 * o3;
                }
            }
        }
    }

    if (STATS) {
        // reduce over gid lanes (same qid): butterfly masks 4,8,16 (deterministic)
        #pragma unroll
        for (int t = 0; t < 8; t++) {
            #pragma unroll
            for (int m = 4; m <= 16; m <<= 1) {
                sarr[t] += __shfl_xor_sync(0xffffffffu, sarr[t], m);
                qarr[t] += __shfl_xor_sync(0xffffffffu, qarr[t], m);
            }
        }
        __syncthreads();                 // done reading As/Bs; reuse as scratch
        float* sS = smemf;               // [2][128]
        float* sQ = smemf + 256;         // [2][128]
        if (gid == 0) {
            #pragma unroll
            for (int t = 0; t < 8; t++) {
                int col = wn * 32 + (t >> 1) * 8 + 2 * qid + (t & 1);
                sS[wm * 128 + col] = sarr[t];
                sQ[wm * 128 + col] = qarr[t];
            }
        }
        __syncthreads();
        if (tid < 128) {
            g_psum[blockIdx.x * 128 + tid] = sS[tid] + sS[128 + tid];
            g_psq[blockIdx.x * 128 + tid] = sQ[tid] + sQ[128 + tid];
        }
    }
}

// ---------------- BN finalize over GB1 partials (deterministic) ----------------
__global__ void bnfinalize_kernel(const float* __restrict__ gamma,
                                  const float* __restrict__ beta) {
    __shared__ float ss[8][128];
    __shared__ float qq[8][128];
    int c = threadIdx.x & 127;
    int chunk = threadIdx.x >> 7;    // 0..7
    float s = 0.f, q = 0.f;
    for (int i = chunk; i < GB1; i += 8) {
        s += g_psum[i * 128 + c];
        q += g_psq[i * 128 + c];
    }
    ss[chunk][c] = s;
    qq[chunk][c] = q;
    __syncthreads();
    if (threadIdx.x < 128) {
        float S = 0.f, Qv = 0.f;
        #pragma unroll
        for (int k = 0; k < 8; k++) { S += ss[k][c]; Qv += qq[k][c]; }
        float mu = S / (float)NN;
        float var = Qv / (float)NN - mu * mu;
        float sc = gamma[c] * rsqrtf(var + BN_EPS);
        g_scale[c] = sc;
        g_shift[c] = beta[c] - mu * sc;
    }
}

// ---------------- pooling (sorted batch -> segmented reduction) + head ----------------
__device__ __forceinline__ int lower_bound_batch(const void* batch, int key) {
    int lo = 0, hi = NN;
    while (lo < hi) {
        int mid = (lo + hi) >> 1;
        int v = load_idx(batch, mid);
        if (v < key) lo = mid + 1; else hi = mid;
    }
    return lo;
}

__global__ void pool_kernel(const float* __restrict__ x, const void* batch) {
    __shared__ int seg[2];
    int g = blockIdx.x;
    int c = threadIdx.x;
    if (c == 0) seg[0] = lower_bound_batch(batch, g);
    if (c == 1) seg[1] = lower_bound_batch(batch, g + 1);
    __syncthreads();
    float acc = 0.f;
    for (int r = seg[0]; r < seg[1]; r++)
        acc += x[(size_t)r * 128 + c];
    g_pooled[g * 128 + c] = acc;
}

__global__ void head_kernel(const float* __restrict__ W1,
                            const float* __restrict__ b1,
                            const float* __restrict__ W2,
                            const float* __restrict__ b2,
                            float* __restrict__ out) {
    __shared__ float pr[128];
    __shared__ float h1[128];
    int g = blockIdx.x;
    int t = threadIdx.x;
    pr[t] = g_pooled[g * 128 + t];
    __syncthreads();
    float s = b1[t];
    #pragma unroll 8
    for (int k = 0; k < 128; k++) s += pr[k] * W1[k * 128 + t];
    h1[t] = fmaxf(s, 0.f);
    __syncthreads();
    if (t < NC) {
        float o = b2[t];
        #pragma unroll 8
        for (int k = 0; k < 128; k++) o += h1[k] * W2[k * NC + t];
        out[g * NC + t] = o;
    }
}

// ---------------- launcher ----------------
extern "C" void kernel_launch(void* const* d_in, const int* in_sizes, int n_in,
                              void* d_out, int out_size) {
    const float* x       = (const float*)d_in[0];
    const void*  ei      = d_in[1];
    const void*  batch   = d_in[2];
    const float* conv_W1 = (const float*)d_in[3];
    const float* conv_b1 = (const float*)d_in[4];
    const float* conv_g  = (const float*)d_in[5];
    const float* conv_bt = (const float*)d_in[6];
    const float* conv_W2 = (const float*)d_in[7];
    const float* conv_b2 = (const float*)d_in[8];
    const float* head_W1 = (const float*)d_in[9];
    const float* head_b1 = (const float*)d_in[10];
    const float* head_W2 = (const float*)d_in[11];
    const float* head_b2 = (const float*)d_in[12];
    float* out = (float*)d_out;

    float *P, *Q, *R, *scale, *shift;
    cudaGetSymbolAddress((void**)&P, g_P);
    cudaGetSymbolAddress((void**)&Q, g_Q);
    cudaGetSymbolAddress((void**)&R, g_R);
    cudaGetSymbolAddress((void**)&scale, g_scale);
    cudaGetSymbolAddress((void**)&shift, g_shift);

    const int SMEM = (64 + 128) * LDT * 4;   // 101376 B
    cudaFuncSetAttribute(gemm64_kernel<false, false, true>,
                         cudaFuncAttributeMaxDynamicSharedMemorySize, SMEM);
    cudaFuncSetAttribute(gemm64_kernel<true, true, false>,
                         cudaFuncAttributeMaxDynamicSharedMemorySize, SMEM);

    // index-width detection
    detect_kernel<<<1, 1>>>((const unsigned*)ei);

    // CSR build (reused by all 5 layers)
    zero_cnt_kernel<<<(NN + 255) / 256, 256>>>();
    count_kernel<<<NE / 256, 256>>>(ei);
    scan_reduce_kernel<<<SCAN_B, 1024>>>();
    scan_bsum_kernel<<<1, 128>>>();
    scan_final_kernel<<<SCAN_B, 1024>>>();
    fill_kernel<<<NE / 256, 256>>>(ei);

    const float* xin = x;
    for (int l = 0; l < NL; l++) {
        // R = xin + sum_neighbors xin   (massively parallel, MLP-4 gather)
        agg_kernel<<<(NN * 32 + 255) / 256, 256>>>(xin, R);
        // Q = R @ W1 + b1, with fused column stats
        gemm64_kernel<false, false, true><<<GB1, 256, SMEM>>>(
            R, conv_W1 + (size_t)l * FD * FD, conv_b1 + l * FD,
            nullptr, nullptr, Q, NN);
        bnfinalize_kernel<<<1, 1024>>>(conv_g + l * FD, conv_bt + l * FD);
        // P = relu( relu(BN(Q)) @ W2 + b2 )
        gemm64_kernel<true, true, false><<<GB1, 256, SMEM>>>(
            Q, conv_W2 + (size_t)l * FD * FD, conv_b2 + l * FD,
            scale, shift, P, NN);
        xin = P;
    }

    pool_kernel<<<NG, 128>>>(P, batch);
    head_kernel<<<NG, 128>>>(head_W1, head_b1, head_W2, head_b2, out);
}

// round 9
// speedup vs baseline: 1.9012x; 1.0493x over previous
#include <cuda_runtime.h>
#include <cuda_fp16.h>
#include <cstdint>

#define NN 100000
#define NE 1600000
#define FD 128
#define NG 512
#define NC 10
#define NL 5
#define BN_EPS 1e-5f
#define SCAN_B 98                  // ceil(NN/1024)
#define LDT 132                    // padded smem stride (words)
#define GB1 ((NN + 63) / 64)       // 1563 GEMM blocks (M-tile 64)

// ---------------- scratch (device globals; no allocs allowed) ----------------
__device__ float    g_P[NN * FD];        // fp32 output of last layer (pooling)
__device__ float    g_Q[NN * FD];        // GEMM1 output (fp32, pre-BN)
__device__ unsigned g_R[NN * FD];        // agg output (tf32 bits)
__device__ __half   g_H[NN * FD];        // fp16 features for gather
__device__ unsigned g_WT[10 * FD * FD];  // pre-transposed tf32 weights [mat][n][k]
__device__ float    g_pooled[NG * FD];
__device__ float    g_psum[GB1 * FD];
__device__ float    g_psq[GB1 * FD];
__device__ float    g_scale[FD];
__device__ float    g_shift[FD];
__device__ int      g_cnt[NN];
__device__ int      g_off[NN + 1];
__device__ int      g_cur[NN];
__device__ int      g_csr[NE];
__device__ int      g_bsum[SCAN_B];
__device__ int      g_boff[SCAN_B];
__device__ int      g_is64;

__device__ __forceinline__ int load_idx(const void* p, long long i) {
    if (g_is64) return (int)((const long long*)p)[i];
    return ((const int*)p)[i];
}

// ---------------- CSR build (zero fused with index-width detect) ----------------
__global__ void zero_cnt_kernel(const unsigned* ei_words) {
    int i = blockIdx.x * blockDim.x + threadIdx.x;
    if (i < NN) g_cnt[i] = 0;
    if (i == 0) {
        int is64 = 1;
        for (int k = 1; k < 64; k++) {
            if (ei_words[2 * k + 1] != 0u) { is64 = 0; break; }
        }
        g_is64 = is64;
    }
}

__global__ void count_kernel(const void* ei) {
    int e = blockIdx.x * blockDim.x + threadIdx.x;
    if (e < NE) {
        int d = load_idx(ei, (long long)NE + e);
        atomicAdd(&g_cnt[d], 1);
    }
}

__global__ void scan_reduce_kernel() {
    int i = blockIdx.x * 1024 + threadIdx.x;
    int v = (i < NN) ? g_cnt[i] : 0;
    __shared__ int ws[32];
    int lane = threadIdx.x & 31, wid = threadIdx.x >> 5;
    #pragma unroll
    for (int d = 16; d > 0; d >>= 1) v += __shfl_down_sync(0xffffffffu, v, d);
    if (lane == 0) ws[wid] = v;
    __syncthreads();
    if (wid == 0) {
        int t = ws[lane];
        #pragma unroll
        for (int d = 16; d > 0; d >>= 1) t += __shfl_down_sync(0xffffffffu, t, d);
        if (lane == 0) g_bsum[blockIdx.x] = t;
    }
}

__global__ void scan_bsum_kernel() {
    __shared__ int s[SCAN_B];
    int t = threadIdx.x;
    if (t < SCAN_B) s[t] = g_bsum[t];
    __syncthreads();
    if (t == 0) {
        int acc = 0;
        for (int i = 0; i < SCAN_B; i++) { g_boff[i] = acc; acc += s[i]; }
        g_off[NN] = acc;
    }
}

__global__ void scan_final_kernel() {
    __shared__ int wsum[32];
    int tid = threadIdx.x, lane = tid & 31, wid = tid >> 5;
    int i = blockIdx.x * 1024 + tid;
    int v = (i < NN) ? g_cnt[i] : 0;
    int incl = v;
    #pragma unroll
    for (int d = 1; d < 32; d <<= 1) {
        int t = __shfl_up_sync(0xffffffffu, incl, d);
        if (lane >= d) incl += t;
    }
    if (lane == 31) wsum[wid] = incl;
    __syncthreads();
    if (wid == 0) {
        int wv = wsum[lane];
        int wincl = wv;
        #pragma unroll
        for (int d = 1; d < 32; d <<= 1) {
            int t = __shfl_up_sync(0xffffffffu, wincl, d);
            if (lane >= d) wincl += t;
        }
        wsum[lane] = wincl - wv;
    }
    __syncthreads();
    if (i < NN) {
        int off = g_boff[blockIdx.x] + wsum[wid] + incl - v;
        g_off[i] = off;
        g_cur[i] = off;
    }
}

__global__ void fill_kernel(const void* ei) {
    int e = blockIdx.x * blockDim.x + threadIdx.x;
    if (e < NE) {
        int s = load_idx(ei, e);
        int d = load_idx(ei, (long long)NE + e);
        int pos = atomicAdd(&g_cur[d], 1);
        g_csr[pos] = s;
    }
}

// ---------------- tf32 helpers ----------------
__device__ __forceinline__ unsigned f2tf(float x) {
    unsigned u;
    asm("cvt.rna.tf32.f32 %0, %1;" : "=r"(u) : "f"(x));
    return u;
}

__device__ __forceinline__ void mma_tf32(float* c, const unsigned* a, const unsigned* b) {
    asm volatile(
        "mma.sync.aligned.m16n8k8.row.col.f32.tf32.tf32.f32 "
        "{%0,%1,%2,%3}, {%4,%5,%6,%7}, {%8,%9}, {%0,%1,%2,%3};"
        : "+f"(c[0]), "+f"(c[1]), "+f"(c[2]), "+f"(c[3])
        : "r"(a[0]), "r"(a[1]), "r"(a[2]), "r"(a[3]), "r"(b[0]), "r"(b[1]));
}

// ---------------- one-time W transpose+cvt: W[k][n] -> g_WT[mat][n][k] (tf32) ----
__global__ void wtrans_kernel(const float* __restrict__ W1,
                              const float* __restrict__ W2) {
    int m = blockIdx.x >> 4, s = blockIdx.x & 15;
    const float* W = (m < 5) ? W1 + (size_t)m * FD * FD
                             : W2 + (size_t)(m - 5) * FD * FD;
    int task = s * 256 + threadIdx.x;   // 0..4095
    int n = task >> 5, k0 = (task & 31) * 4;
    uint4 u = make_uint4(f2tf(__ldg(&W[(k0 + 0) * 128 + n])),
                         f2tf(__ldg(&W[(k0 + 1) * 128 + n])),
                         f2tf(__ldg(&W[(k0 + 2) * 128 + n])),
                         f2tf(__ldg(&W[(k0 + 3) * 128 + n])));
    *(uint4*)&g_WT[(size_t)m * 16384 + n * 128 + k0] = u;
}

// ---------------- fp32 -> fp16 feature convert (layer-0 input) ----------------
__global__ void tohalf_kernel(const float2* __restrict__ x, __half2* __restrict__ h) {
    int i = blockIdx.x * blockDim.x + threadIdx.x;
    if (i < NN * FD / 2) {
        float2 v = x[i];
        h[i] = __floats2half2_rn(v.x, v.y);
    }
}

// ---------------- edge aggregation (fp16 in, tf32 out) ----------------
// out[n] = tf32( f32(h[n]) + sum_{j->n} f32(h[j]) ); 1 warp/node, MLP-4 unroll.
__device__ __forceinline__ float4 h4_to_f4(uint2 u) {
    __half2 h0 = *(__half2*)&u.x;
    __half2 h1 = *(__half2*)&u.y;
    float2 f0 = __half22float2(h0);
    float2 f1 = __half22float2(h1);
    return make_float4(f0.x, f0.y, f1.x, f1.y);
}

__global__ __launch_bounds__(256) void agg_kernel(const __half2* __restrict__ xh,
                                                  unsigned* __restrict__ out) {
    int w = (blockIdx.x * blockDim.x + threadIdx.x) >> 5;
    int lane = threadIdx.x & 31;
    if (w >= NN) return;
    const uint2* xv = (const uint2*)xh;       // 32 uint2 per row (128 halves)
    float4 acc = h4_to_f4(__ldg(&xv[(size_t)w * 32 + lane]));
    int s = g_off[w], e = g_off[w + 1];
    int i = s;
    for (; i + 4 <= e; i += 4) {
        int n0 = __ldg(&g_csr[i + 0]);
        int n1 = __ldg(&g_csr[i + 1]);
        int n2 = __ldg(&g_csr[i + 2]);
        int n3 = __ldg(&g_csr[i + 3]);
        float4 v0 = h4_to_f4(__ldg(&xv[(size_t)n0 * 32 + lane]));
        float4 v1 = h4_to_f4(__ldg(&xv[(size_t)n1 * 32 + lane]));
        float4 v2 = h4_to_f4(__ldg(&xv[(size_t)n2 * 32 + lane]));
        float4 v3 = h4_to_f4(__ldg(&xv[(size_t)n3 * 32 + lane]));
        acc.x += v0.x + v1.x + v2.x + v3.x;
        acc.y += v0.y + v1.y + v2.y + v3.y;
        acc.z += v0.z + v1.z + v2.z + v3.z;
        acc.w += v0.w + v1.w + v2.w + v3.w;
    }
    for (; i < e; i++) {
        int nb = __ldg(&g_csr[i]);
        float4 v = h4_to_f4(__ldg(&xv[(size_t)nb * 32 + lane]));
        acc.x += v.x; acc.y += v.y; acc.z += v.z; acc.w += v.w;
    }
    uint4 o = make_uint4(f2tf(acc.x), f2tf(acc.y), f2tf(acc.z), f2tf(acc.w));
    ((uint4*)out)[(size_t)w * 32 + lane] = o;
}

// ---------------- tf32 GEMM, M-tile 64 ----------------
// A_RAW:   A already holds tf32 bits (agg output) -> raw copy
// PRE_BN:  per-column affine + relu on A rows (fused batchnorm)
// OUT_RELU: relu on output
// STATS:   per-block column sum/sumsq partials of the output
// OUT_HALF: write half2 to Ch instead of float2 to C
template <bool A_RAW, bool PRE_BN, bool OUT_RELU, bool STATS, bool OUT_HALF>
__global__ __launch_bounds__(256) void gemm64_kernel(
    const float* __restrict__ A, const unsigned* __restrict__ WT,
    const float* __restrict__ bias,
    const float* __restrict__ scale, const float* __restrict__ shift,
    float* __restrict__ C, __half* __restrict__ Ch, int M) {
    extern __shared__ float smemf[];
    unsigned* As = (unsigned*)smemf;          // 64 x LDT
    unsigned* Bs = As + 64 * LDT;             // 128 x LDT (n-major: Bs[n*LDT+k])
    int tid = threadIdx.x;
    int r0 = blockIdx.x * 64;

    // Bs: coalesced uint4 copy of pre-transposed tf32 W^T (no cvt, no stride)
    #pragma unroll
    for (int i = 0; i < 16; i++) {
        int idx = tid + i * 256;         // 0..4095 uint4
        uint4 u = ((const uint4*)WT)[idx];
        int n = idx >> 5, c4 = idx & 31;
        *(uint4*)&Bs[n * LDT + c4 * 4] = u;
    }
    // A tile -> As (raw tf32 copy, or fp32 + fused BN affine + relu + cvt)
    #pragma unroll
    for (int i = 0; i < 8; i++) {
        int f4 = tid + i * 256;          // 0..2047
        int row = f4 >> 5, c4 = f4 & 31;
        uint4 u = make_uint4(0u, 0u, 0u, 0u);
        if (A_RAW) {
            if (r0 + row < M)
                u = ((const uint4*)((const unsigned*)A + (size_t)(r0 + row) * 128))[c4];
        } else {
            float4 v = make_float4(0.f, 0.f, 0.f, 0.f);
            if (r0 + row < M)
                v = ((const float4*)(A + (size_t)(r0 + row) * 128))[c4];
            if (PRE_BN) {
                int c = c4 * 4;
                v.x = fmaxf(v.x * __ldg(&scale[c + 0]) + __ldg(&shift[c + 0]), 0.f);
                v.y = fmaxf(v.y * __ldg(&scale[c + 1]) + __ldg(&shift[c + 1]), 0.f);
                v.z = fmaxf(v.z * __ldg(&scale[c + 2]) + __ldg(&shift[c + 2]), 0.f);
                v.w = fmaxf(v.w * __ldg(&scale[c + 3]) + __ldg(&shift[c + 3]), 0.f);
            }
            u = make_uint4(f2tf(v.x), f2tf(v.y), f2tf(v.z), f2tf(v.w));
        }
        *(uint4*)&As[row * LDT + c4 * 4] = u;
    }
    __syncthreads();

    int wid = tid >> 5, lane = tid & 31;
    int wm = wid >> 2, wn = wid & 3;     // 2 (M) x 4 (N) warps; warp tile 32x32
    int gid = lane >> 2, qid = lane & 3;

    float c[2][4][4];
    #pragma unroll
    for (int mi = 0; mi < 2; mi++)
        #pragma unroll
        for (int ni = 0; ni < 4; ni++)
            #pragma unroll
            for (int j = 0; j < 4; j++) c[mi][ni][j] = 0.f;

    #pragma unroll
    for (int kk = 0; kk < 16; kk++) {
        int k0 = kk * 8;
        unsigned a[2][4];
        #pragma unroll
        for (int mi = 0; mi < 2; mi++) {
            int r = wm * 32 + mi * 16 + gid;
            a[mi][0] = As[r * LDT + k0 + qid];
            a[mi][1] = As[(r + 8) * LDT + k0 + qid];
            a[mi][2] = As[r * LDT + k0 + qid + 4];
            a[mi][3] = As[(r + 8) * LDT + k0 + qid + 4];
        }
        unsigned b[4][2];
        #pragma unroll
        for (int ni = 0; ni < 4; ni++) {
            int n = wn * 32 + ni * 8 + gid;
            b[ni][0] = Bs[n * LDT + k0 + qid];
            b[ni][1] = Bs[n * LDT + k0 + qid + 4];
        }
        #pragma unroll
        for (int mi = 0; mi < 2; mi++)
            #pragma unroll
            for (int ni = 0; ni < 4; ni++)
                mma_tf32(c[mi][ni], a[mi], b[ni]);
    }

    // ---- epilogue: bias (+relu), stores; optional column-stat partials ----
    float sarr[8], qarr[8];
    if (STATS) {
        #pragma unroll
        for (int t = 0; t < 8; t++) { sarr[t] = 0.f; qarr[t] = 0.f; }
    }
    #pragma unroll
    for (int ni = 0; ni < 4; ni++) {
        int col = wn * 32 + ni * 8 + 2 * qid;
        float b0 = __ldg(&bias[col]);
        float b1 = __ldg(&bias[col + 1]);
        #pragma unroll
        for (int mi = 0; mi < 2; mi++) {
            int gr = r0 + wm * 32 + mi * 16 + gid;
            float o0 = c[mi][ni][0] + b0;
            float o1 = c[mi][ni][1] + b1;
            float o2 = c[mi][ni][2] + b0;
            float o3 = c[mi][ni][3] + b1;
            if (OUT_RELU) {
                o0 = fmaxf(o0, 0.f); o1 = fmaxf(o1, 0.f);
                o2 = fmaxf(o2, 0.f); o3 = fmaxf(o3, 0.f);
            }
            if (gr < M) {
                if (OUT_HALF)
                    ((__half2*)Ch)[(size_t)gr * 64 + (col >> 1)] = __floats2half2_rn(o0, o1);
                else
                    *(float2*)(C + (size_t)gr * 128 + col) = make_float2(o0, o1);
                if (STATS) {
                    sarr[ni * 2 + 0] += o0; qarr[ni * 2 + 0] += o0 * o0;
                    sarr[ni * 2 + 1] += o1; qarr[ni * 2 + 1] += o1 * o1;
                }
            }
            if (gr + 8 < M) {
                if (OUT_HALF)
                    ((__half2*)Ch)[(size_t)(gr + 8) * 64 + (col >> 1)] = __floats2half2_rn(o2, o3);
                else
                    *(float2*)(C + (size_t)(gr + 8) * 128 + col) = make_float2(o2, o3);
                if (STATS) {
                    sarr[ni * 2 + 0] += o2; qarr[ni * 2 + 0] += o2 * o2;
                    sarr[ni * 2 + 1] += o3; qarr[ni * 2 + 1] += o3 * o3;
                }
            }
        }
    }

    if (STATS) {
        // reduce over gid lanes (same qid): butterfly masks 4,8,16 (deterministic)
        #pragma unroll
        for (int t = 0; t < 8; t++) {
            #pragma unroll
            for (int m = 4; m <= 16; m <<= 1) {
                sarr[t] += __shfl_xor_sync(0xffffffffu, sarr[t], m);
                qarr[t] += __shfl_xor_sync(0xffffffffu, qarr[t], m);
            }
        }
        __syncthreads();                 // done reading As/Bs; reuse as scratch
        float* sS = smemf;               // [2][128]
        float* sQ = smemf + 256;         // [2][128]
        if (gid == 0) {
            #pragma unroll
            for (int t = 0; t < 8; t++) {
                int col = wn * 32 + (t >> 1) * 8 + 2 * qid + (t & 1);
                sS[wm * 128 + col] = sarr[t];
                sQ[wm * 128 + col] = qarr[t];
            }
        }
        __syncthreads();
        if (tid < 128) {
            g_psum[blockIdx.x * 128 + tid] = sS[tid] + sS[128 + tid];
            g_psq[blockIdx.x * 128 + tid] = sQ[tid] + sQ[128 + tid];
        }
    }
}

// ---------------- BN finalize over GB1 partials (deterministic) ----------------
__global__ void bnfinalize_kernel(const float* __restrict__ gamma,
                                  const float* __restrict__ beta) {
    __shared__ float ss[8][128];
    __shared__ float qq[8][128];
    int c = threadIdx.x & 127;
    int chunk = threadIdx.x >> 7;    // 0..7
    float s = 0.f, q = 0.f;
    for (int i = chunk; i < GB1; i += 8) {
        s += g_psum[i * 128 + c];
        q += g_psq[i * 128 + c];
    }
    ss[chunk][c] = s;
    qq[chunk][c] = q;
    __syncthreads();
    if (threadIdx.x < 128) {
        float S = 0.f, Qv = 0.f;
        #pragma unroll
        for (int k = 0; k < 8; k++) { S += ss[k][c]; Qv += qq[k][c]; }
        float mu = S / (float)NN;
        float var = Qv / (float)NN - mu * mu;
        float sc = gamma[c] * rsqrtf(var + BN_EPS);
        g_scale[c] = sc;
        g_shift[c] = beta[c] - mu * sc;
    }
}

// ---------------- pooling (sorted batch -> segmented reduction) + head ----------------
__device__ __forceinline__ int lower_bound_batch(const void* batch, int key) {
    int lo = 0, hi = NN;
    while (lo < hi) {
        int mid = (lo + hi) >> 1;
        int v = load_idx(batch, mid);
        if (v < key) lo = mid + 1; else hi = mid;
    }
    return lo;
}

__global__ void pool_kernel(const float* __restrict__ x, const void* batch) {
    __shared__ int seg[2];
    int g = blockIdx.x;
    int c = threadIdx.x;
    if (c == 0) seg[0] = lower_bound_batch(batch, g);
    if (c == 1) seg[1] = lower_bound_batch(batch, g + 1);
    __syncthreads();
    float acc = 0.f;
    for (int r = seg[0]; r < seg[1]; r++)
        acc += x[(size_t)r * 128 + c];
    g_pooled[g * 128 + c] = acc;
}

__global__ void head_kernel(const float* __restrict__ W1,
                            const float* __restrict__ b1,
                            const float* __restrict__ W2,
                            const float* __restrict__ b2,
                            float* __restrict__ out) {
    __shared__ float pr[128];
    __shared__ float h1[128];
    int g = blockIdx.x;
    int t = threadIdx.x;
    pr[t] = g_pooled[g * 128 + t];
    __syncthreads();
    float s = b1[t];
    #pragma unroll 8
    for (int k = 0; k < 128; k++) s += pr[k] * W1[k * 128 + t];
    h1[t] = fmaxf(s, 0.f);
    __syncthreads();
    if (t < NC) {
        float o = b2[t];
        #pragma unroll 8
        for (int k = 0; k < 128; k++) o += h1[k] * W2[k * NC + t];
        out[g * NC + t] = o;
    }
}

// ---------------- launcher ----------------
extern "C" void kernel_launch(void* const* d_in, const int* in_sizes, int n_in,
                              void* d_out, int out_size) {
    const float* x       = (const float*)d_in[0];
    const void*  ei      = d_in[1];
    const void*  batch   = d_in[2];
    const float* conv_W1 = (const float*)d_in[3];
    const float* conv_b1 = (const float*)d_in[4];
    const float* conv_g  = (const float*)d_in[5];
    const float* conv_bt = (const float*)d_in[6];
    const float* conv_W2 = (const float*)d_in[7];
    const float* conv_b2 = (const float*)d_in[8];
    const float* head_W1 = (const float*)d_in[9];
    const float* head_b1 = (const float*)d_in[10];
    const float* head_W2 = (const float*)d_in[11];
    const float* head_b2 = (const float*)d_in[12];
    float* out = (float*)d_out;

    float *P, *Q, *scale, *shift;
    unsigned *R, *WT;
    __half *H;
    cudaGetSymbolAddress((void**)&P, g_P);
    cudaGetSymbolAddress((void**)&Q, g_Q);
    cudaGetSymbolAddress((void**)&R, g_R);
    cudaGetSymbolAddress((void**)&H, g_H);
    cudaGetSymbolAddress((void**)&WT, g_WT);
    cudaGetSymbolAddress((void**)&scale, g_scale);
    cudaGetSymbolAddress((void**)&shift, g_shift);

    const int SMEM = (64 + 128) * LDT * 4;   // 101376 B
    cudaFuncSetAttribute(gemm64_kernel<true, false, false, true, false>,
                         cudaFuncAttributeMaxDynamicSharedMemorySize, SMEM);
    cudaFuncSetAttribute(gemm64_kernel<false, true, true, false, true>,
                         cudaFuncAttributeMaxDynamicSharedMemorySize, SMEM);
    cudaFuncSetAttribute(gemm64_kernel<false, true, true, false, false>,
                         cudaFuncAttributeMaxDynamicSharedMemorySize, SMEM);

    // CSR build (reused by all 5 layers); zero_cnt also does index-width detect
    zero_cnt_kernel<<<(NN + 255) / 256, 256>>>((const unsigned*)ei);
    count_kernel<<<NE / 256, 256>>>(ei);
    scan_reduce_kernel<<<SCAN_B, 1024>>>();
    scan_bsum_kernel<<<1, 128>>>();
    scan_final_kernel<<<SCAN_B, 1024>>>();
    fill_kernel<<<NE / 256, 256>>>(ei);

    // one-time: pre-transpose weights; convert layer-0 features to fp16
    wtrans_kernel<<<160, 256>>>(conv_W1, conv_W2);
    tohalf_kernel<<<(NN * FD / 2 + 255) / 256, 256>>>((const float2*)x, (__half2*)H);

    for (int l = 0; l < NL; l++) {
        // R = tf32( H + sum_neighbors H )
        agg_kernel<<<(NN * 32 + 255) / 256, 256>>>((const __half2*)H, R);
        // Q = R @ W1 + b1, with fused column stats
        gemm64_kernel<true, false, false, true, false><<<GB1, 256, SMEM>>>(
            (const float*)R, WT + (size_t)l * 16384, conv_b1 + l * FD,
            nullptr, nullptr, Q, nullptr, NN);
        bnfinalize_kernel<<<1, 1024>>>(conv_g + l * FD, conv_bt + l * FD);
        // out = relu( relu(BN(Q)) @ W2 + b2 ): fp16 for next gather, fp32 last
        if (l < NL - 1) {
            gemm64_kernel<false, true, true, false, true><<<GB1, 256, SMEM>>>(
                Q, WT + (size_t)(5 + l) * 16384, conv_b2 + l * FD,
                scale, shift, nullptr, H, NN);
        } else {
            gemm64_kernel<false, true, true, false, false><<<GB1, 256, SMEM>>>(
                Q, WT + (size_t)(5 + l) * 16384, conv_b2 + l * FD,
                scale, shift, P, nullptr, NN);
        }
    }

    pool_kernel<<<NG, 128>>>(P, batch);
    head_kernel<<<NG, 128>>>(head_W1, head_b1, head_W2, head_b2, out);
}

// round 10
// speedup vs baseline: 2.4284x; 1.2773x over previous
#include <cuda_runtime.h>
#include <cuda_fp16.h>
#include <cstdint>

#define NN 100000
#define NE 1600000
#define FD 128
#define NG 512
#define NC 10
#define NL 5
#define BN_EPS 1e-5f
#define SCAN_B 98                  // ceil(NN/1024)
#define LDH 68                     // padded smem stride (uint32 = 2 halves)
#define GB1 ((NN + 63) / 64)       // 1563 GEMM blocks (M-tile 64)

// ---------------- scratch (device globals; no allocs allowed) ----------------
__device__ float    g_P[NN * FD];        // fp32 output of last layer (pooling)
__device__ float    g_Q[NN * FD];        // GEMM1 output (fp32, pre-BN)
__device__ __half   g_R[NN * FD];        // agg output (fp16)
__device__ __half   g_H[NN * FD];        // fp16 features for gather
__device__ __half   g_WT[10 * FD * FD];  // pre-transposed fp16 weights [mat][n][k]
__device__ float    g_pooled[NG * FD];
__device__ float    g_psum[GB1 * FD];
__device__ float    g_psq[GB1 * FD];
__device__ float    g_scale[FD];
__device__ float    g_shift[FD];
__device__ int      g_cnt[NN];
__device__ int      g_off[NN + 1];
__device__ int      g_cur[NN];
__device__ int      g_csr[NE];
__device__ int      g_bsum[SCAN_B];
__device__ int      g_boff[SCAN_B];
__device__ int      g_is64;

__device__ __forceinline__ int load_idx(const void* p, long long i) {
    if (g_is64) return (int)((const long long*)p)[i];
    return ((const int*)p)[i];
}

// ---------------- CSR build (zero fused with index-width detect) ----------------
__global__ void zero_cnt_kernel(const unsigned* ei_words) {
    int i = blockIdx.x * blockDim.x + threadIdx.x;
    if (i < NN) g_cnt[i] = 0;
    if (i == 0) {
        int is64 = 1;
        for (int k = 1; k < 64; k++) {
            if (ei_words[2 * k + 1] != 0u) { is64 = 0; break; }
        }
        g_is64 = is64;
    }
}

__global__ void count_kernel(const void* ei) {
    int e = blockIdx.x * blockDim.x + threadIdx.x;
    if (e < NE) {
        int d = load_idx(ei, (long long)NE + e);
        atomicAdd(&g_cnt[d], 1);
    }
}

__global__ void scan_reduce_kernel() {
    int i = blockIdx.x * 1024 + threadIdx.x;
    int v = (i < NN) ? g_cnt[i] : 0;
    __shared__ int ws[32];
    int lane = threadIdx.x & 31, wid = threadIdx.x >> 5;
    #pragma unroll
    for (int d = 16; d > 0; d >>= 1) v += __shfl_down_sync(0xffffffffu, v, d);
    if (lane == 0) ws[wid] = v;
    __syncthreads();
    if (wid == 0) {
        int t = ws[lane];
        #pragma unroll
        for (int d = 16; d > 0; d >>= 1) t += __shfl_down_sync(0xffffffffu, t, d);
        if (lane == 0) g_bsum[blockIdx.x] = t;
    }
}

__global__ void scan_bsum_kernel() {
    __shared__ int s[SCAN_B];
    int t = threadIdx.x;
    if (t < SCAN_B) s[t] = g_bsum[t];
    __syncthreads();
    if (t == 0) {
        int acc = 0;
        for (int i = 0; i < SCAN_B; i++) { g_boff[i] = acc; acc += s[i]; }
        g_off[NN] = acc;
    }
}

__global__ void scan_final_kernel() {
    __shared__ int wsum[32];
    int tid = threadIdx.x, lane = tid & 31, wid = tid >> 5;
    int i = blockIdx.x * 1024 + tid;
    int v = (i < NN) ? g_cnt[i] : 0;
    int incl = v;
    #pragma unroll
    for (int d = 1; d < 32; d <<= 1) {
        int t = __shfl_up_sync(0xffffffffu, incl, d);
        if (lane >= d) incl += t;
    }
    if (lane == 31) wsum[wid] = incl;
    __syncthreads();
    if (wid == 0) {
        int wv = wsum[lane];
        int wincl = wv;
        #pragma unroll
        for (int d = 1; d < 32; d <<= 1) {
            int t = __shfl_up_sync(0xffffffffu, wincl, d);
            if (lane >= d) wincl += t;
        }
        wsum[lane] = wincl - wv;
    }
    __syncthreads();
    if (i < NN) {
        int off = g_boff[blockIdx.x] + wsum[wid] + incl - v;
        g_off[i] = off;
        g_cur[i] = off;
    }
}

__global__ void fill_kernel(const void* ei) {
    int e = blockIdx.x * blockDim.x + threadIdx.x;
    if (e < NE) {
        int s = load_idx(ei, e);
        int d = load_idx(ei, (long long)NE + e);
        int pos = atomicAdd(&g_cur[d], 1);
        g_csr[pos] = s;
    }
}

// ---------------- fp16 mma helper ----------------
__device__ __forceinline__ void mma_f16(float* c, const unsigned* a, const unsigned* b) {
    asm volatile(
        "mma.sync.aligned.m16n8k16.row.col.f32.f16.f16.f32 "
        "{%0,%1,%2,%3}, {%4,%5,%6,%7}, {%8,%9}, {%0,%1,%2,%3};"
        : "+f"(c[0]), "+f"(c[1]), "+f"(c[2]), "+f"(c[3])
        : "r"(a[0]), "r"(a[1]), "r"(a[2]), "r"(a[3]), "r"(b[0]), "r"(b[1]));
}

// ---------------- one-time W transpose+cvt: W[k][n] -> g_WT[mat][n][k] fp16 ----
__global__ void wtrans_kernel(const float* __restrict__ W1,
                              const float* __restrict__ W2) {
    int m = blockIdx.x >> 4, s = blockIdx.x & 15;
    const float* W = (m < 5) ? W1 + (size_t)m * FD * FD
                             : W2 + (size_t)(m - 5) * FD * FD;
    int task = s * 256 + threadIdx.x;   // 0..4095 (each: 4 k-values at one n)
    int n = task >> 5, k0 = (task & 31) * 4;
    __half2 p0 = __floats2half2_rn(__ldg(&W[(k0 + 0) * 128 + n]),
                                   __ldg(&W[(k0 + 1) * 128 + n]));
    __half2 p1 = __floats2half2_rn(__ldg(&W[(k0 + 2) * 128 + n]),
                                   __ldg(&W[(k0 + 3) * 128 + n]));
    uint2 o;
    o.x = *reinterpret_cast<unsigned*>(&p0);
    o.y = *reinterpret_cast<unsigned*>(&p1);
    *(uint2*)&g_WT[(size_t)m * 16384 + n * 128 + k0] = o;
}

// ---------------- fp32 -> fp16 feature convert (layer-0 input) ----------------
__global__ void tohalf_kernel(const float2* __restrict__ x, __half2* __restrict__ h) {
    int i = blockIdx.x * blockDim.x + threadIdx.x;
    if (i < NN * FD / 2) {
        float2 v = x[i];
        h[i] = __floats2half2_rn(v.x, v.y);
    }
}

// ---------------- edge aggregation (fp16 in, fp32 accum, fp16 out) ------------
__device__ __forceinline__ float4 h4_to_f4(uint2 u) {
    __half2 h0 = *(__half2*)&u.x;
    __half2 h1 = *(__half2*)&u.y;
    float2 f0 = __half22float2(h0);
    float2 f1 = __half22float2(h1);
    return make_float4(f0.x, f0.y, f1.x, f1.y);
}

__global__ __launch_bounds__(256) void agg_kernel(const __half* __restrict__ xh,
                                                  __half* __restrict__ out) {
    int w = (blockIdx.x * blockDim.x + threadIdx.x) >> 5;
    int lane = threadIdx.x & 31;
    if (w >= NN) return;
    const uint2* xv = (const uint2*)xh;       // 32 uint2 per row (128 halves)
    float4 acc = h4_to_f4(__ldg(&xv[(size_t)w * 32 + lane]));
    int s = g_off[w], e = g_off[w + 1];
    int i = s;
    for (; i + 4 <= e; i += 4) {
        int n0 = __ldg(&g_csr[i + 0]);
        int n1 = __ldg(&g_csr[i + 1]);
        int n2 = __ldg(&g_csr[i + 2]);
        int n3 = __ldg(&g_csr[i + 3]);
        float4 v0 = h4_to_f4(__ldg(&xv[(size_t)n0 * 32 + lane]));
        float4 v1 = h4_to_f4(__ldg(&xv[(size_t)n1 * 32 + lane]));
        float4 v2 = h4_to_f4(__ldg(&xv[(size_t)n2 * 32 + lane]));
        float4 v3 = h4_to_f4(__ldg(&xv[(size_t)n3 * 32 + lane]));
        acc.x += v0.x + v1.x + v2.x + v3.x;
        acc.y += v0.y + v1.y + v2.y + v3.y;
        acc.z += v0.z + v1.z + v2.z + v3.z;
        acc.w += v0.w + v1.w + v2.w + v3.w;
    }
    for (; i < e; i++) {
        int nb = __ldg(&g_csr[i]);
        float4 v = h4_to_f4(__ldg(&xv[(size_t)nb * 32 + lane]));
        acc.x += v.x; acc.y += v.y; acc.z += v.z; acc.w += v.w;
    }
    __half2 p0 = __floats2half2_rn(acc.x, acc.y);
    __half2 p1 = __floats2half2_rn(acc.z, acc.w);
    uint2 o;
    o.x = *reinterpret_cast<unsigned*>(&p0);
    o.y = *reinterpret_cast<unsigned*>(&p1);
    ((uint2*)out)[(size_t)w * 32 + lane] = o;
}

// ---------------- fp16 tensor-core GEMM, M-tile 64 ----------------
// A_HALF:  A is fp16 rows (agg output) -> raw uint4 copy into As
// PRE_BN:  A is fp32; apply per-column affine + relu, then cvt to fp16
// OUT_RELU / STATS / OUT_HALF as before. Accumulation fp32.
template <bool A_HALF, bool PRE_BN, bool OUT_RELU, bool STATS, bool OUT_HALF>
__global__ __launch_bounds__(256) void gemm64h_kernel(
    const void* __restrict__ Ain, const __half* __restrict__ WT,
    const float* __restrict__ bias,
    const float* __restrict__ scale, const float* __restrict__ shift,
    float* __restrict__ C, __half* __restrict__ Ch, int M) {
    extern __shared__ float smemf[];
    unsigned* As = (unsigned*)smemf;          // 64 x LDH (uint32 = 2 halves)
    unsigned* Bs = As + 64 * LDH;             // 128 x LDH (n-major: [n][k])
    int tid = threadIdx.x;
    int r0 = blockIdx.x * 64;

    // Bs: coalesced uint4 copy of pre-transposed fp16 W^T (2048 uint4)
    #pragma unroll
    for (int i = 0; i < 8; i++) {
        int idx4 = tid + i * 256;        // 0..2047
        uint4 u = ((const uint4*)WT)[idx4];
        int n = idx4 >> 4, koff = (idx4 & 15) * 4;
        *(uint4*)&Bs[n * LDH + koff] = u;
    }
    if (A_HALF) {
        // raw copy of fp16 rows (1024 uint4)
        const __half* Ah = (const __half*)Ain;
        #pragma unroll
        for (int i = 0; i < 4; i++) {
            int idx4 = tid + i * 256;    // 0..1023
            int row = idx4 >> 4, koff = (idx4 & 15) * 4;
            uint4 u = make_uint4(0u, 0u, 0u, 0u);
            if (r0 + row < M)
                u = ((const uint4*)(Ah + (size_t)(r0 + row) * 128))[idx4 & 15];
            *(uint4*)&As[row * LDH + koff] = u;
        }
    } else {
        // fp32 rows + fused BN affine + relu -> fp16
        const float* Af = (const float*)Ain;
        #pragma unroll
        for (int i = 0; i < 8; i++) {
            int f4 = tid + i * 256;      // 0..2047
            int row = f4 >> 5, c4 = f4 & 31;
            float4 v = make_float4(0.f, 0.f, 0.f, 0.f);
            if (r0 + row < M)
                v = ((const float4*)(Af + (size_t)(r0 + row) * 128))[c4];
            if (PRE_BN) {
                int c = c4 * 4;
                v.x = fmaxf(v.x * __ldg(&scale[c + 0]) + __ldg(&shift[c + 0]), 0.f);
                v.y = fmaxf(v.y * __ldg(&scale[c + 1]) + __ldg(&shift[c + 1]), 0.f);
                v.z = fmaxf(v.z * __ldg(&scale[c + 2]) + __ldg(&shift[c + 2]), 0.f);
                v.w = fmaxf(v.w * __ldg(&scale[c + 3]) + __ldg(&shift[c + 3]), 0.f);
            }
            __half2 p0 = __floats2half2_rn(v.x, v.y);
            __half2 p1 = __floats2half2_rn(v.z, v.w);
            uint2 o;
            o.x = *reinterpret_cast<unsigned*>(&p0);
            o.y = *reinterpret_cast<unsigned*>(&p1);
            *(uint2*)&As[row * LDH + c4 * 2] = o;
        }
    }
    __syncthreads();

    int wid = tid >> 5, lane = tid & 31;
    int wm = wid >> 2, wn = wid & 3;     // 2 (M) x 4 (N) warps; warp tile 32x32
    int gid = lane >> 2, qid = lane & 3;

    float c[2][4][4];
    #pragma unroll
    for (int mi = 0; mi < 2; mi++)
        #pragma unroll
        for (int ni = 0; ni < 4; ni++)
            #pragma unroll
            for (int j = 0; j < 4; j++) c[mi][ni][j] = 0.f;

    #pragma unroll
    for (int kk = 0; kk < 8; kk++) {
        int k0 = kk * 8;                 // uint32 offset = 16 halves
        unsigned a[2][4];
        #pragma unroll
        for (int mi = 0; mi < 2; mi++) {
            int r = wm * 32 + mi * 16 + gid;
            a[mi][0] = As[r * LDH + k0 + qid];
            a[mi][1] = As[(r + 8) * LDH + k0 + qid];
            a[mi][2] = As[r * LDH + k0 + 4 + qid];
            a[mi][3] = As[(r + 8) * LDH + k0 + 4 + qid];
        }
        unsigned b[4][2];
        #pragma unroll
        for (int ni = 0; ni < 4; ni++) {
            int n = wn * 32 + ni * 8 + gid;
            b[ni][0] = Bs[n * LDH + k0 + qid];
            b[ni][1] = Bs[n * LDH + k0 + 4 + qid];
        }
        #pragma unroll
        for (int mi = 0; mi < 2; mi++)
            #pragma unroll
            for (int ni = 0; ni < 4; ni++)
                mma_f16(c[mi][ni], a[mi], b[ni]);
    }

    // ---- epilogue: bias (+relu), stores; optional column-stat partials ----
    float sarr[8], qarr[8];
    if (STATS) {
        #pragma unroll
        for (int t = 0; t < 8; t++) { sarr[t] = 0.f; qarr[t] = 0.f; }
    }
    #pragma unroll
    for (int ni = 0; ni < 4; ni++) {
        int col = wn * 32 + ni * 8 + 2 * qid;
        float b0 = __ldg(&bias[col]);
        float b1 = __ldg(&bias[col + 1]);
        #pragma unroll
        for (int mi = 0; mi < 2; mi++) {
            int gr = r0 + wm * 32 + mi * 16 + gid;
            float o0 = c[mi][ni][0] + b0;
            float o1 = c[mi][ni][1] + b1;
            float o2 = c[mi][ni][2] + b0;
            float o3 = c[mi][ni][3] + b1;
            if (OUT_RELU) {
                o0 = fmaxf(o0, 0.f); o1 = fmaxf(o1, 0.f);
                o2 = fmaxf(o2, 0.f); o3 = fmaxf(o3, 0.f);
            }
            if (gr < M) {
                if (OUT_HALF)
                    ((__half2*)Ch)[(size_t)gr * 64 + (col >> 1)] = __floats2half2_rn(o0, o1);
                else
                    *(float2*)(C + (size_t)gr * 128 + col) = make_float2(o0, o1);
                if (STATS) {
                    sarr[ni * 2 + 0] += o0; qarr[ni * 2 + 0] += o0 * o0;
                    sarr[ni * 2 + 1] += o1; qarr[ni * 2 + 1] += o1 * o1;
                }
            }
            if (gr + 8 < M) {
                if (OUT_HALF)
                    ((__half2*)Ch)[(size_t)(gr + 8) * 64 + (col >> 1)] = __floats2half2_rn(o2, o3);
                else
                    *(float2*)(C + (size_t)(gr + 8) * 128 + col) = make_float2(o2, o3);
                if (STATS) {
                    sarr[ni * 2 + 0] += o2; qarr[ni * 2 + 0] += o2 * o2;
                    sarr[ni * 2 + 1] += o3; qarr[ni * 2 + 1] += o3 * o3;
                }
            }
        }
    }

    if (STATS) {
        // reduce over gid lanes (same qid): butterfly masks 4,8,16 (deterministic)
        #pragma unroll
        for (int t = 0; t < 8; t++) {
            #pragma unroll
            for (int m = 4; m <= 16; m <<= 1) {
                sarr[t] += __shfl_xor_sync(0xffffffffu, sarr[t], m);
                qarr[t] += __shfl_xor_sync(0xffffffffu, qarr[t], m);
            }
        }
        __syncthreads();                 // done reading As/Bs; reuse as scratch
        float* sS = smemf;               // [2][128]
        float* sQ = smemf + 256;         // [2][128]
        if (gid == 0) {
            #pragma unroll
            for (int t = 0; t < 8; t++) {
                int col = wn * 32 + (t >> 1) * 8 + 2 * qid + (t & 1);
                sS[wm * 128 + col] = sarr[t];
                sQ[wm * 128 + col] = qarr[t];
            }
        }
        __syncthreads();
        if (tid < 128) {
            g_psum[blockIdx.x * 128 + tid] = sS[tid] + sS[128 + tid];
            g_psq[blockIdx.x * 128 + tid] = sQ[tid] + sQ[128 + tid];
        }
    }
}

// ---------------- BN finalize over GB1 partials (deterministic) ----------------
__global__ void bnfinalize_kernel(const float* __restrict__ gamma,
                                  const float* __restrict__ beta) {
    __shared__ float ss[8][128];
    __shared__ float qq[8][128];
    int c = threadIdx.x & 127;
    int chunk = threadIdx.x >> 7;    // 0..7
    float s = 0.f, q = 0.f;
    for (int i = chunk; i < GB1; i += 8) {
        s += g_psum[i * 128 + c];
        q += g_psq[i * 128 + c];
    }
    ss[chunk][c] = s;
    qq[chunk][c] = q;
    __syncthreads();
    if (threadIdx.x < 128) {
        float S = 0.f, Qv = 0.f;
        #pragma unroll
        for (int k = 0; k < 8; k++) { S += ss[k][c]; Qv += qq[k][c]; }
        float mu = S / (float)NN;
        float var = Qv / (float)NN - mu * mu;
        float sc = gamma[c] * rsqrtf(var + BN_EPS);
        g_scale[c] = sc;
        g_shift[c] = beta[c] - mu * sc;
    }
}

// ---------------- pooling (sorted batch -> segmented reduction) + head ----------------
__device__ __forceinline__ int lower_bound_batch(const void* batch, int key) {
    int lo = 0, hi = NN;
    while (lo < hi) {
        int mid = (lo + hi) >> 1;
        int v = load_idx(batch, mid);
        if (v < key) lo = mid + 1; else hi = mid;
    }
    return lo;
}

__global__ void pool_kernel(const float* __restrict__ x, const void* batch) {
    __shared__ int seg[2];
    int g = blockIdx.x;
    int c = threadIdx.x;
    if (c == 0) seg[0] = lower_bound_batch(batch, g);
    if (c == 1) seg[1] = lower_bound_batch(batch, g + 1);
    __syncthreads();
    float acc = 0.f;
    for (int r = seg[0]; r < seg[1]; r++)
        acc += x[(size_t)r * 128 + c];
    g_pooled[g * 128 + c] = acc;
}

__global__ void head_kernel(const float* __restrict__ W1,
                            const float* __restrict__ b1,
                            const float* __restrict__ W2,
                            const float* __restrict__ b2,
                            float* __restrict__ out) {
    __shared__ float pr[128];
    __shared__ float h1[128];
    int g = blockIdx.x;
    int t = threadIdx.x;
    pr[t] = g_pooled[g * 128 + t];
    __syncthreads();
    float s = b1[t];
    #pragma unroll 8
    for (int k = 0; k < 128; k++) s += pr[k] * W1[k * 128 + t];
    h1[t] = fmaxf(s, 0.f);
    __syncthreads();
    if (t < NC) {
        float o = b2[t];
        #pragma unroll 8
        for (int k = 0; k < 128; k++) o += h1[k] * W2[k * NC + t];
        out[g * NC + t] = o;
    }
}

// ---------------- launcher ----------------
extern "C" void kernel_launch(void* const* d_in, const int* in_sizes, int n_in,
                              void* d_out, int out_size) {
    const float* x       = (const float*)d_in[0];
    const void*  ei      = d_in[1];
    const void*  batch   = d_in[2];
    const float* conv_W1 = (const float*)d_in[3];
    const float* conv_b1 = (const float*)d_in[4];
    const float* conv_g  = (const float*)d_in[5];
    const float* conv_bt = (const float*)d_in[6];
    const float* conv_W2 = (const float*)d_in[7];
    const float* conv_b2 = (const float*)d_in[8];
    const float* head_W1 = (const float*)d_in[9];
    const float* head_b1 = (const float*)d_in[10];
    const float* head_W2 = (const float*)d_in[11];
    const float* head_b2 = (const float*)d_in[12];
    float* out = (float*)d_out;

    float *P, *Q, *scale, *shift;
    __half *R, *H, *WT;
    cudaGetSymbolAddress((void**)&P, g_P);
    cudaGetSymbolAddress((void**)&Q, g_Q);
    cudaGetSymbolAddress((void**)&R, g_R);
    cudaGetSymbolAddress((void**)&H, g_H);
    cudaGetSymbolAddress((void**)&WT, g_WT);
    cudaGetSymbolAddress((void**)&scale, g_scale);
    cudaGetSymbolAddress((void**)&shift, g_shift);

    const int SMEM = (64 + 128) * LDH * 4;   // 52224 B
    cudaFuncSetAttribute(gemm64h_kernel<true, false, false, true, false>,
                         cudaFuncAttributeMaxDynamicSharedMemorySize, SMEM);
    cudaFuncSetAttribute(gemm64h_kernel<false, true, true, false, true>,
                         cudaFuncAttributeMaxDynamicSharedMemorySize, SMEM);
    cudaFuncSetAttribute(gemm64h_kernel<false, true, true, false, false>,
                         cudaFuncAttributeMaxDynamicSharedMemorySize, SMEM);

    // CSR build (reused by all 5 layers); zero_cnt also does index-width detect
    zero_cnt_kernel<<<(NN + 255) / 256, 256>>>((const unsigned*)ei);
    count_kernel<<<NE / 256, 256>>>(ei);
    scan_reduce_kernel<<<SCAN_B, 1024>>>();
    scan_bsum_kernel<<<1, 128>>>();
    scan_final_kernel<<<SCAN_B, 1024>>>();
    fill_kernel<<<NE / 256, 256>>>(ei);

    // one-time: pre-transpose weights to fp16; convert layer-0 features to fp16
    wtrans_kernel<<<160, 256>>>(conv_W1, conv_W2);
    tohalf_kernel<<<(NN * FD / 2 + 255) / 256, 256>>>((const float2*)x, (__half2*)H);

    for (int l = 0; l < NL; l++) {
        // R = fp16( H + sum_neighbors H )
        agg_kernel<<<(NN * 32 + 255) / 256, 256>>>(H, R);
        // Q = R @ W1 + b1 (fp32 out), with fused column stats
        gemm64h_kernel<true, false, false, true, false><<<GB1, 256, SMEM>>>(
            R, WT + (size_t)l * 16384, conv_b1 + l * FD,
            nullptr, nullptr, Q, nullptr, NN);
        bnfinalize_kernel<<<1, 1024>>>(conv_g + l * FD, conv_bt + l * FD);
        // out = relu( relu(BN(Q)) @ W2 + b2 ): fp16 for next gather, fp32 last
        if (l < NL - 1) {
            gemm64h_kernel<false, true, true, false, true><<<GB1, 256, SMEM>>>(
                Q, WT + (size_t)(5 + l) * 16384, conv_b2 + l * FD,
                scale, shift, nullptr, H, NN);
        } else {
            gemm64h_kernel<false, true, true, false, false><<<GB1, 256, SMEM>>>(
                Q, WT + (size_t)(5 + l) * 16384, conv_b2 + l * FD,
                scale, shift, P, nullptr, NN);
        }
    }

    pool_kernel<<<NG, 128>>>(P, batch);
    head_kernel<<<NG, 128>>>(head_W1, head_b1, head_W2, head_b2, out);
}

// round 11
// speedup vs baseline: 2.5514x; 1.0507x over previous
#include <cuda_runtime.h>
#include <cuda_fp16.h>
#include <cstdint>

#define NN 100000
#define NE 1600000
#define FD 128
#define NG 512
#define NC 10
#define NL 5
#define BN_EPS 1e-5f
#define SCAN_B 98                  // ceil(NN/1024)
#define LDH 68                     // padded smem stride (uint32 = 2 halves)
#define GB1 ((NN + 63) / 64)       // 1563 GEMM blocks (M-tile 64)

// ---------------- scratch (device globals; no allocs allowed) ----------------
__device__ float    g_P[NN * FD];        // fp32 output of last layer (pooling)
__device__ __half   g_Q[NN * FD];        // GEMM1 output (fp16, pre-BN)
__device__ __half   g_R[NN * FD];        // agg output (fp16)
__device__ __half   g_H[NN * FD];        // fp16 features for gather
__device__ __half   g_WT[10 * FD * FD];  // pre-transposed fp16 weights [mat][n][k]
__device__ float    g_psum[GB1 * FD];
__device__ float    g_psq[GB1 * FD];
__device__ float    g_scale[FD];
__device__ float    g_shift[FD];
__device__ int      g_cnt[NN];
__device__ int      g_off[NN + 1];
__device__ int      g_cur[NN];
__device__ int      g_csr[NE];
__device__ int      g_bsum[SCAN_B];
__device__ int      g_is64;

__device__ __forceinline__ int load_idx(const void* p, long long i) {
    if (g_is64) return (int)((const long long*)p)[i];
    return ((const int*)p)[i];
}

// ---------------- CSR build (zero fused with index-width detect) ----------------
__global__ void zero_cnt_kernel(const unsigned* ei_words) {
    int i = blockIdx.x * blockDim.x + threadIdx.x;
    if (i < NN) g_cnt[i] = 0;
    if (i == 0) {
        int is64 = 1;
        for (int k = 1; k < 64; k++) {
            if (ei_words[2 * k + 1] != 0u) { is64 = 0; break; }
        }
        g_is64 = is64;
    }
}

__global__ void count_kernel(const void* ei) {
    int e = blockIdx.x * blockDim.x + threadIdx.x;
    if (e < NE) {
        int d = load_idx(ei, (long long)NE + e);
        atomicAdd(&g_cnt[d], 1);
    }
}

__global__ void scan_reduce_kernel() {
    int i = blockIdx.x * 1024 + threadIdx.x;
    int v = (i < NN) ? g_cnt[i] : 0;
    __shared__ int ws[32];
    int lane = threadIdx.x & 31, wid = threadIdx.x >> 5;
    #pragma unroll
    for (int d = 16; d > 0; d >>= 1) v += __shfl_down_sync(0xffffffffu, v, d);
    if (lane == 0) ws[wid] = v;
    __syncthreads();
    if (wid == 0) {
        int t = ws[lane];
        #pragma unroll
        for (int d = 16; d > 0; d >>= 1) t += __shfl_down_sync(0xffffffffu, t, d);
        if (lane == 0) g_bsum[blockIdx.x] = t;
    }
}

// block-local scan + serial per-block prefix of g_bsum (scan_bsum folded in)
__global__ void scan_final_kernel() {
    __shared__ int wsum[32];
    __shared__ int carry;
    int tid = threadIdx.x, lane = tid & 31, wid = tid >> 5;
    if (tid == 0) {
        int acc = 0;
        for (int j = 0; j < blockIdx.x; j++) acc += g_bsum[j];
        carry = acc;
        if (blockIdx.x == SCAN_B - 1) {
            int tot = acc;
            for (int j = blockIdx.x; j < SCAN_B; j++) tot += g_bsum[j];
            g_off[NN] = tot;
        }
    }
    int i = blockIdx.x * 1024 + tid;
    int v = (i < NN) ? g_cnt[i] : 0;
    int incl = v;
    #pragma unroll
    for (int d = 1; d < 32; d <<= 1) {
        int t = __shfl_up_sync(0xffffffffu, incl, d);
        if (lane >= d) incl += t;
    }
    if (lane == 31) wsum[wid] = incl;
    __syncthreads();
    if (wid == 0) {
        int wv = wsum[lane];
        int wincl = wv;
        #pragma unroll
        for (int d = 1; d < 32; d <<= 1) {
            int t = __shfl_up_sync(0xffffffffu, wincl, d);
            if (lane >= d) wincl += t;
        }
        wsum[lane] = wincl - wv;
    }
    __syncthreads();
    if (i < NN) {
        int off = carry + wsum[wid] + incl - v;
        g_off[i] = off;
        g_cur[i] = off;
    }
}

__global__ void fill_kernel(const void* ei) {
    int e = blockIdx.x * blockDim.x + threadIdx.x;
    if (e < NE) {
        int s = load_idx(ei, e);
        int d = load_idx(ei, (long long)NE + e);
        int pos = atomicAdd(&g_cur[d], 1);
        g_csr[pos] = s;
    }
}

// ---------------- fp16 mma helper ----------------
__device__ __forceinline__ void mma_f16(float* c, const unsigned* a, const unsigned* b) {
    asm volatile(
        "mma.sync.aligned.m16n8k16.row.col.f32.f16.f16.f32 "
        "{%0,%1,%2,%3}, {%4,%5,%6,%7}, {%8,%9}, {%0,%1,%2,%3};"
        : "+f"(c[0]), "+f"(c[1]), "+f"(c[2]), "+f"(c[3])
        : "r"(a[0]), "r"(a[1]), "r"(a[2]), "r"(a[3]), "r"(b[0]), "r"(b[1]));
}

// ---------------- one-time prep: W transpose->fp16 + x->fp16 ----------------
__global__ void prep_kernel(const float* __restrict__ W1,
                            const float* __restrict__ W2,
                            const float2* __restrict__ x,
                            __half2* __restrict__ h) {
    int b = blockIdx.x;
    if (b < 160) {
        int m = b >> 4, s = b & 15;
        const float* W = (m < 5) ? W1 + (size_t)m * FD * FD
                                 : W2 + (size_t)(m - 5) * FD * FD;
        int task = s * 256 + threadIdx.x;   // 0..4095 (4 k-values at one n)
        int n = task >> 5, k0 = (task & 31) * 4;
        __half2 p0 = __floats2half2_rn(__ldg(&W[(k0 + 0) * 128 + n]),
                                       __ldg(&W[(k0 + 1) * 128 + n]));
        __half2 p1 = __floats2half2_rn(__ldg(&W[(k0 + 2) * 128 + n]),
                                       __ldg(&W[(k0 + 3) * 128 + n]));
        uint2 o;
        o.x = *reinterpret_cast<unsigned*>(&p0);
        o.y = *reinterpret_cast<unsigned*>(&p1);
        *(uint2*)&g_WT[(size_t)m * 16384 + n * 128 + k0] = o;
    } else {
        int i = (b - 160) * 256 + threadIdx.x;
        if (i < NN * FD / 2) {
            float2 v = x[i];
            h[i] = __floats2half2_rn(v.x, v.y);
        }
    }
}

// ---------------- edge aggregation (fp16 in, HADD2 tree, fp32 acc, fp16 out) --
__device__ __forceinline__ float4 h4_to_f4(uint2 u) {
    __half2 h0 = *(__half2*)&u.x;
    __half2 h1 = *(__half2*)&u.y;
    float2 f0 = __half22float2(h0);
    float2 f1 = __half22float2(h1);
    return make_float4(f0.x, f0.y, f1.x, f1.y);
}

__global__ __launch_bounds__(256) void agg_kernel(const __half* __restrict__ xh,
                                                  __half* __restrict__ out) {
    int w = (blockIdx.x * blockDim.x + threadIdx.x) >> 5;
    int lane = threadIdx.x & 31;
    if (w >= NN) return;
    const uint2* xv = (const uint2*)xh;       // 32 uint2 per row (128 halves)
    float4 acc = h4_to_f4(__ldg(&xv[(size_t)w * 32 + lane]));
    int s = g_off[w], e = g_off[w + 1];
    int i = s;
    for (; i + 4 <= e; i += 4) {
        int n0 = __ldg(&g_csr[i + 0]);
        int n1 = __ldg(&g_csr[i + 1]);
        int n2 = __ldg(&g_csr[i + 2]);
        int n3 = __ldg(&g_csr[i + 3]);
        uint2 u0 = __ldg(&xv[(size_t)n0 * 32 + lane]);
        uint2 u1 = __ldg(&xv[(size_t)n1 * 32 + lane]);
        uint2 u2 = __ldg(&xv[(size_t)n2 * 32 + lane]);
        uint2 u3 = __ldg(&xv[(size_t)n3 * 32 + lane]);
        // pairwise fp16 tree (2 rounding levels), then fp32 accumulate
        __half2 plo = __hadd2(__hadd2(*(__half2*)&u0.x, *(__half2*)&u1.x),
                              __hadd2(*(__half2*)&u2.x, *(__half2*)&u3.x));
        __half2 phi = __hadd2(__hadd2(*(__half2*)&u0.y, *(__half2*)&u1.y),
                              __hadd2(*(__half2*)&u2.y, *(__half2*)&u3.y));
        float2 flo = __half22float2(plo);
        float2 fhi = __half22float2(phi);
        acc.x += flo.x; acc.y += flo.y; acc.z += fhi.x; acc.w += fhi.y;
    }
    for (; i < e; i++) {
        int nb = __ldg(&g_csr[i]);
        float4 v = h4_to_f4(__ldg(&xv[(size_t)nb * 32 + lane]));
        acc.x += v.x; acc.y += v.y; acc.z += v.z; acc.w += v.w;
    }
    __half2 p0 = __floats2half2_rn(acc.x, acc.y);
    __half2 p1 = __floats2half2_rn(acc.z, acc.w);
    uint2 o;
    o.x = *reinterpret_cast<unsigned*>(&p0);
    o.y = *reinterpret_cast<unsigned*>(&p1);
    ((uint2*)out)[(size_t)w * 32 + lane] = o;
}

// ---------------- fp16 tensor-core GEMM, M-tile 64 (A always fp16) -----------
// PRE_BN:  per-column affine + relu applied while staging A
// OUT_RELU / STATS / OUT_HALF as before. Accumulation fp32.
template <bool PRE_BN, bool OUT_RELU, bool STATS, bool OUT_HALF>
__global__ __launch_bounds__(256) void gemm64h_kernel(
    const __half* __restrict__ A, const __half* __restrict__ WT,
    const float* __restrict__ bias,
    const float* __restrict__ scale, const float* __restrict__ shift,
    float* __restrict__ C, __half* __restrict__ Ch, int M) {
    extern __shared__ float smemf[];
    unsigned* As = (unsigned*)smemf;          // 64 x LDH (uint32 = 2 halves)
    unsigned* Bs = As + 64 * LDH;             // 128 x LDH (n-major: [n][k])
    int tid = threadIdx.x;
    int r0 = blockIdx.x * 64;

    // Bs: coalesced uint4 copy of pre-transposed fp16 W^T (2048 uint4)
    #pragma unroll
    for (int i = 0; i < 8; i++) {
        int idx4 = tid + i * 256;        // 0..2047
        uint4 u = ((const uint4*)WT)[idx4];
        int n = idx4 >> 4, koff = (idx4 & 15) * 4;
        *(uint4*)&Bs[n * LDH + koff] = u;
    }
    // As: fp16 rows; optional fused BN affine + relu (unpack/affine/repack)
    #pragma unroll
    for (int i = 0; i < 4; i++) {
        int idx4 = tid + i * 256;        // 0..1023
        int row = idx4 >> 4, q4 = idx4 & 15;
        uint4 u = make_uint4(0u, 0u, 0u, 0u);
        if (r0 + row < M)
            u = ((const uint4*)(A + (size_t)(r0 + row) * 128))[q4];
        if (PRE_BN) {
            int c = q4 * 8;
            float2 f0 = __half22float2(*(__half2*)&u.x);
            float2 f1 = __half22float2(*(__half2*)&u.y);
            float2 f2 = __half22float2(*(__half2*)&u.z);
            float2 f3 = __half22float2(*(__half2*)&u.w);
            f0.x = fmaxf(f0.x * __ldg(&scale[c + 0]) + __ldg(&shift[c + 0]), 0.f);
            f0.y = fmaxf(f0.y * __ldg(&scale[c + 1]) + __ldg(&shift[c + 1]), 0.f);
            f1.x = fmaxf(f1.x * __ldg(&scale[c + 2]) + __ldg(&shift[c + 2]), 0.f);
            f1.y = fmaxf(f1.y * __ldg(&scale[c + 3]) + __ldg(&shift[c + 3]), 0.f);
            f2.x = fmaxf(f2.x * __ldg(&scale[c + 4]) + __ldg(&shift[c + 4]), 0.f);
            f2.y = fmaxf(f2.y * __ldg(&scale[c + 5]) + __ldg(&shift[c + 5]), 0.f);
            f3.x = fmaxf(f3.x * __ldg(&scale[c + 6]) + __ldg(&shift[c + 6]), 0.f);
            f3.y = fmaxf(f3.y * __ldg(&scale[c + 7]) + __ldg(&shift[c + 7]), 0.f);
            __half2 p0 = __floats2half2_rn(f0.x, f0.y);
            __half2 p1 = __floats2half2_rn(f1.x, f1.y);
            __half2 p2 = __floats2half2_rn(f2.x, f2.y);
            __half2 p3 = __floats2half2_rn(f3.x, f3.y);
            u.x = *reinterpret_cast<unsigned*>(&p0);
            u.y = *reinterpret_cast<unsigned*>(&p1);
            u.z = *reinterpret_cast<unsigned*>(&p2);
            u.w = *reinterpret_cast<unsigned*>(&p3);
        }
        *(uint4*)&As[row * LDH + q4 * 4] = u;
    }
    __syncthreads();

    int wid = tid >> 5, lane = tid & 31;
    int wm = wid >> 2, wn = wid & 3;     // 2 (M) x 4 (N) warps; warp tile 32x32
    int gid = lane >> 2, qid = lane & 3;

    float c[2][4][4];
    #pragma unroll
    for (int mi = 0; mi < 2; mi++)
        #pragma unroll
        for (int ni = 0; ni < 4; ni++)
            #pragma unroll
            for (int j = 0; j < 4; j++) c[mi][ni][j] = 0.f;

    #pragma unroll
    for (int kk = 0; kk < 8; kk++) {
        int k0 = kk * 8;                 // uint32 offset = 16 halves
        unsigned a[2][4];
        #pragma unroll
        for (int mi = 0; mi < 2; mi++) {
            int r = wm * 32 + mi * 16 + gid;
            a[mi][0] = As[r * LDH + k0 + qid];
            a[mi][1] = As[(r + 8) * LDH + k0 + qid];
            a[mi][2] = As[r * LDH + k0 + 4 + qid];
            a[mi][3] = As[(r + 8) * LDH + k0 + 4 + qid];
        }
        unsigned b[4][2];
        #pragma unroll
        for (int ni = 0; ni < 4; ni++) {
            int n = wn * 32 + ni * 8 + gid;
            b[ni][0] = Bs[n * LDH + k0 + qid];
            b[ni][1] = Bs[n * LDH + k0 + 4 + qid];
        }
        #pragma unroll
        for (int mi = 0; mi < 2; mi++)
            #pragma unroll
            for (int ni = 0; ni < 4; ni++)
                mma_f16(c[mi][ni], a[mi], b[ni]);
    }

    // ---- epilogue: bias (+relu), stores; optional column-stat partials ----
    float sarr[8], qarr[8];
    if (STATS) {
        #pragma unroll
        for (int t = 0; t < 8; t++) { sarr[t] = 0.f; qarr[t] = 0.f; }
    }
    #pragma unroll
    for (int ni = 0; ni < 4; ni++) {
        int col = wn * 32 + ni * 8 + 2 * qid;
        float b0 = __ldg(&bias[col]);
        float b1 = __ldg(&bias[col + 1]);
        #pragma unroll
        for (int mi = 0; mi < 2; mi++) {
            int gr = r0 + wm * 32 + mi * 16 + gid;
            float o0 = c[mi][ni][0] + b0;
            float o1 = c[mi][ni][1] + b1;
            float o2 = c[mi][ni][2] + b0;
            float o3 = c[mi][ni][3] + b1;
            if (OUT_RELU) {
                o0 = fmaxf(o0, 0.f); o1 = fmaxf(o1, 0.f);
                o2 = fmaxf(o2, 0.f); o3 = fmaxf(o3, 0.f);
            }
            if (gr < M) {
                if (OUT_HALF)
                    ((__half2*)Ch)[(size_t)gr * 64 + (col >> 1)] = __floats2half2_rn(o0, o1);
                else
                    *(float2*)(C + (size_t)gr * 128 + col) = make_float2(o0, o1);
                if (STATS) {
                    sarr[ni * 2 + 0] += o0; qarr[ni * 2 + 0] += o0 * o0;
                    sarr[ni * 2 + 1] += o1; qarr[ni * 2 + 1] += o1 * o1;
                }
            }
            if (gr + 8 < M) {
                if (OUT_HALF)
                    ((__half2*)Ch)[(size_t)(gr + 8) * 64 + (col >> 1)] = __floats2half2_rn(o2, o3);
                else
                    *(float2*)(C + (size_t)(gr + 8) * 128 + col) = make_float2(o2, o3);
                if (STATS) {
                    sarr[ni * 2 + 0] += o2; qarr[ni * 2 + 0] += o2 * o2;
                    sarr[ni * 2 + 1] += o3; qarr[ni * 2 + 1] += o3 * o3;
                }
            }
        }
    }

    if (STATS) {
        // reduce over gid lanes (same qid): butterfly masks 4,8,16 (deterministic)
        #pragma unroll
        for (int t = 0; t < 8; t++) {
            #pragma unroll
            for (int m = 4; m <= 16; m <<= 1) {
                sarr[t] += __shfl_xor_sync(0xffffffffu, sarr[t], m);
                qarr[t] += __shfl_xor_sync(0xffffffffu, qarr[t], m);
            }
        }
        __syncthreads();                 // done reading As/Bs; reuse as scratch
        float* sS = smemf;               // [2][128]
        float* sQ = smemf + 256;         // [2][128]
        if (gid == 0) {
            #pragma unroll
            for (int t = 0; t < 8; t++) {
                int col = wn * 32 + (t >> 1) * 8 + 2 * qid + (t & 1);
                sS[wm * 128 + col] = sarr[t];
                sQ[wm * 128 + col] = qarr[t];
            }
        }
        __syncthreads();
        if (tid < 128) {
            g_psum[blockIdx.x * 128 + tid] = sS[tid] + sS[128 + tid];
            g_psq[blockIdx.x * 128 + tid] = sQ[tid] + sQ[128 + tid];
        }
    }
}

// ---------------- BN finalize over GB1 partials (deterministic) ----------------
__global__ void bnfinalize_kernel(const float* __restrict__ gamma,
                                  const float* __restrict__ beta) {
    __shared__ float ss[8][128];
    __shared__ float qq[8][128];
    int c = threadIdx.x & 127;
    int chunk = threadIdx.x >> 7;    // 0..7
    float s = 0.f, q = 0.f;
    for (int i = chunk; i < GB1; i += 8) {
        s += g_psum[i * 128 + c];
        q += g_psq[i * 128 + c];
    }
    ss[chunk][c] = s;
    qq[chunk][c] = q;
    __syncthreads();
    if (threadIdx.x < 128) {
        float S = 0.f, Qv = 0.f;
        #pragma unroll
        for (int k = 0; k < 8; k++) { S += ss[k][c]; Qv += qq[k][c]; }
        float mu = S / (float)NN;
        float var = Qv / (float)NN - mu * mu;
        float sc = gamma[c] * rsqrtf(var + BN_EPS);
        g_scale[c] = sc;
        g_shift[c] = beta[c] - mu * sc;
    }
}

// ---------------- fused pooling + head MLP (block per graph) ----------------
__device__ __forceinline__ int lower_bound_batch(const void* batch, int key) {
    int lo = 0, hi = NN;
    while (lo < hi) {
        int mid = (lo + hi) >> 1;
        int v = load_idx(batch, mid);
        if (v < key) lo = mid + 1; else hi = mid;
    }
    return lo;
}

__global__ void poolhead_kernel(const float* __restrict__ x, const void* batch,
                                const float* __restrict__ W1,
                                const float* __restrict__ b1,
                                const float* __restrict__ W2,
                                const float* __restrict__ b2,
                                float* __restrict__ out) {
    __shared__ float pr[128];
    __shared__ float h1[128];
    __shared__ int seg[2];
    int g = blockIdx.x;
    int c = threadIdx.x;
    if (c < 2) seg[c] = lower_bound_batch(batch, g + c);
    __syncthreads();
    float acc = 0.f;
    for (int r = seg[0]; r < seg[1]; r++)
        acc += x[(size_t)r * 128 + c];
    pr[c] = acc;
    __syncthreads();
    float s = b1[c];
    #pragma unroll 8
    for (int k = 0; k < 128; k++) s += pr[k] * W1[k * 128 + c];
    h1[c] = fmaxf(s, 0.f);
    __syncthreads();
    if (c < NC) {
        float o = b2[c];
        #pragma unroll 8
        for (int k = 0; k < 128; k++) o += h1[k] * W2[k * NC + c];
        out[g * NC + c] = o;
    }
}

// ---------------- launcher ----------------
extern "C" void kernel_launch(void* const* d_in, const int* in_sizes, int n_in,
                              void* d_out, int out_size) {
    const float* x       = (const float*)d_in[0];
    const void*  ei      = d_in[1];
    const void*  batch   = d_in[2];
    const float* conv_W1 = (const float*)d_in[3];
    const float* conv_b1 = (const float*)d_in[4];
    const float* conv_g  = (const float*)d_in[5];
    const float* conv_bt = (const float*)d_in[6];
    const float* conv_W2 = (const float*)d_in[7];
    const float* conv_b2 = (const float*)d_in[8];
    const float* head_W1 = (const float*)d_in[9];
    const float* head_b1 = (const float*)d_in[10];
    const float* head_W2 = (const float*)d_in[11];
    const float* head_b2 = (const float*)d_in[12];
    float* out = (float*)d_out;

    float *P, *scale, *shift;
    __half *Q, *R, *H, *WT;
    cudaGetSymbolAddress((void**)&P, g_P);
    cudaGetSymbolAddress((void**)&Q, g_Q);
    cudaGetSymbolAddress((void**)&R, g_R);
    cudaGetSymbolAddress((void**)&H, g_H);
    cudaGetSymbolAddress((void**)&WT, g_WT);
    cudaGetSymbolAddress((void**)&scale, g_scale);
    cudaGetSymbolAddress((void**)&shift, g_shift);

    const int SMEM = (64 + 128) * LDH * 4;   // 52224 B
    cudaFuncSetAttribute(gemm64h_kernel<false, false, true, true>,
                         cudaFuncAttributeMaxDynamicSharedMemorySize, SMEM);
    cudaFuncSetAttribute(gemm64h_kernel<true, true, false, true>,
                         cudaFuncAttributeMaxDynamicSharedMemorySize, SMEM);
    cudaFuncSetAttribute(gemm64h_kernel<true, true, false, false>,
                         cudaFuncAttributeMaxDynamicSharedMemorySize, SMEM);

    // CSR build (reused by all 5 layers); zero_cnt also does index-width detect
    zero_cnt_kernel<<<(NN + 255) / 256, 256>>>((const unsigned*)ei);
    count_kernel<<<NE / 256, 256>>>(ei);
    scan_reduce_kernel<<<SCAN_B, 1024>>>();
    scan_final_kernel<<<SCAN_B, 1024>>>();
    fill_kernel<<<NE / 256, 256>>>(ei);

    // one-time: W transpose->fp16 + layer-0 features->fp16 (merged)
    prep_kernel<<<160 + (NN * FD / 2 + 255) / 256, 256>>>(
        conv_W1, conv_W2, (const float2*)x, (__half2*)H);

    for (int l = 0; l < NL; l++) {
        // R = fp16( H + sum_neighbors H )  [HADD2 tree, fp32 carry]
        agg_kernel<<<(NN * 32 + 255) / 256, 256>>>(H, R);
        // Q = fp16( R @ W1 + b1 ), with fused fp32 column stats
        gemm64h_kernel<false, false, true, true><<<GB1, 256, SMEM>>>(
            R, WT + (size_t)l * 16384, conv_b1 + l * FD,
            nullptr, nullptr, nullptr, Q, NN);
        bnfinalize_kernel<<<1, 1024>>>(conv_g + l * FD, conv_bt + l * FD);
        // out = relu( relu(BN(Q)) @ W2 + b2 ): fp16 for next gather, fp32 last
        if (l < NL - 1) {
            gemm64h_kernel<true, true, false, true><<<GB1, 256, SMEM>>>(
                Q, WT + (size_t)(5 + l) * 16384, conv_b2 + l * FD,
                scale, shift, nullptr, H, NN);
        } else {
            gemm64h_kernel<true, true, false, false><<<GB1, 256, SMEM>>>(
                Q, WT + (size_t)(5 + l) * 16384, conv_b2 + l * FD,
                scale, shift, P, nullptr, NN);
        }
    }

    poolhead_kernel<<<NG, 128>>>(P, batch, head_W1, head_b1, head_W2, head_b2, out);
}

// round 12
// speedup vs baseline: 2.8812x; 1.1292x over previous
#include <cuda_runtime.h>
#include <cuda_fp16.h>
#include <cstdint>

#define NN 100000
#define NE 1600000
#define FD 128
#define NG 512
#define NC 10
#define NL 5
#define BN_EPS 1e-5f
#define SCAN_B 98                  // ceil(NN/1024)
#define LDH 68                     // padded smem stride (uint32 = 2 halves)
#define MT 128                     // GEMM M-tile
#define GB1 ((NN + MT - 1) / MT)   // 782 GEMM blocks

// ---------------- scratch (device globals; no allocs allowed) ----------------
__device__ float    g_P[NN * FD];        // fp32 output of last layer (pooling)
__device__ __half   g_Q[NN * FD];        // GEMM1 output (fp16, pre-BN)
__device__ __half   g_R[NN * FD];        // agg output (fp16)
__device__ __half   g_H[NN * FD];        // fp16 features for gather
__device__ __half   g_WT[10 * FD * FD];  // pre-transposed fp16 weights [mat][n][k]
__device__ float    g_psum[GB1 * FD];
__device__ float    g_psq[GB1 * FD];
__device__ float    g_scale[FD];
__device__ float    g_shift[FD];
__device__ int      g_cnt[NN];
__device__ int      g_off[NN + 1];
__device__ int      g_cur[NN];
__device__ int      g_csr[NE];
__device__ int      g_bsum[SCAN_B];
__device__ int      g_is64;

__device__ __forceinline__ int load_idx(const void* p, long long i) {
    if (g_is64) return (int)((const long long*)p)[i];
    return ((const int*)p)[i];
}

// ---------------- launch 0: zero counts + x->fp16 + index-width detect ---------
__global__ void zero_prep_kernel(const unsigned* ei_words,
                                 const float2* __restrict__ x,
                                 __half2* __restrict__ h) {
    int i = blockIdx.x * 256 + threadIdx.x;
    if (i < NN * FD / 2) {
        float2 v = x[i];
        h[i] = __floats2half2_rn(v.x, v.y);
    }
    if (i < NN) g_cnt[i] = 0;
    if (i == 0) {
        int is64 = 1;
        for (int k = 1; k < 64; k++) {
            if (ei_words[2 * k + 1] != 0u) { is64 = 0; break; }
        }
        g_is64 = is64;
    }
}

// ---------------- launch 1: degree count + W transpose->fp16 -------------------
__global__ void count_kernel(const void* ei,
                             const float* __restrict__ W1,
                             const float* __restrict__ W2) {
    int b = blockIdx.x;
    if (b < NE / 256) {
        int e = b * 256 + threadIdx.x;
        int d = load_idx(ei, (long long)NE + e);
        atomicAdd(&g_cnt[d], 1);
    } else {
        int wb = b - NE / 256;              // 0..159
        int m = wb >> 4, s = wb & 15;
        const float* W = (m < 5) ? W1 + (size_t)m * FD * FD
                                 : W2 + (size_t)(m - 5) * FD * FD;
        int task = s * 256 + threadIdx.x;   // 0..4095 (4 k-values at one n)
        int n = task >> 5, k0 = (task & 31) * 4;
        __half2 p0 = __floats2half2_rn(__ldg(&W[(k0 + 0) * 128 + n]),
                                       __ldg(&W[(k0 + 1) * 128 + n]));
        __half2 p1 = __floats2half2_rn(__ldg(&W[(k0 + 2) * 128 + n]),
                                       __ldg(&W[(k0 + 3) * 128 + n]));
        uint2 o;
        o.x = *reinterpret_cast<unsigned*>(&p0);
        o.y = *reinterpret_cast<unsigned*>(&p1);
        *(uint2*)&g_WT[(size_t)m * 16384 + n * 128 + k0] = o;
    }
}

__global__ void scan_reduce_kernel() {
    int i = blockIdx.x * 1024 + threadIdx.x;
    int v = (i < NN) ? g_cnt[i] : 0;
    __shared__ int ws[32];
    int lane = threadIdx.x & 31, wid = threadIdx.x >> 5;
    #pragma unroll
    for (int d = 16; d > 0; d >>= 1) v += __shfl_down_sync(0xffffffffu, v, d);
    if (lane == 0) ws[wid] = v;
    __syncthreads();
    if (wid == 0) {
        int t = ws[lane];
        #pragma unroll
        for (int d = 16; d > 0; d >>= 1) t += __shfl_down_sync(0xffffffffu, t, d);
        if (lane == 0) g_bsum[blockIdx.x] = t;
    }
}

// block-local scan + serial per-block prefix of g_bsum
__global__ void scan_final_kernel() {
    __shared__ int wsum[32];
    __shared__ int carry;
    int tid = threadIdx.x, lane = tid & 31, wid = tid >> 5;
    if (tid == 0) {
        int acc = 0;
        for (int j = 0; j < blockIdx.x; j++) acc += g_bsum[j];
        carry = acc;
        if (blockIdx.x == SCAN_B - 1) {
            int tot = acc;
            for (int j = blockIdx.x; j < SCAN_B; j++) tot += g_bsum[j];
            g_off[NN] = tot;
        }
    }
    int i = blockIdx.x * 1024 + tid;
    int v = (i < NN) ? g_cnt[i] : 0;
    int incl = v;
    #pragma unroll
    for (int d = 1; d < 32; d <<= 1) {
        int t = __shfl_up_sync(0xffffffffu, incl, d);
        if (lane >= d) incl += t;
    }
    if (lane == 31) wsum[wid] = incl;
    __syncthreads();
    if (wid == 0) {
        int wv = wsum[lane];
        int wincl = wv;
        #pragma unroll
        for (int d = 1; d < 32; d <<= 1) {
            int t = __shfl_up_sync(0xffffffffu, wincl, d);
            if (lane >= d) wincl += t;
        }
        wsum[lane] = wincl - wv;
    }
    __syncthreads();
    if (i < NN) {
        int off = carry + wsum[wid] + incl - v;
        g_off[i] = off;
        g_cur[i] = off;
    }
}

__global__ void fill_kernel(const void* ei) {
    int e = blockIdx.x * blockDim.x + threadIdx.x;
    if (e < NE) {
        int s = load_idx(ei, e);
        int d = load_idx(ei, (long long)NE + e);
        int pos = atomicAdd(&g_cur[d], 1);
        g_csr[pos] = s;
    }
}

// ---------------- fp16 mma helper ----------------
__device__ __forceinline__ void mma_f16(float* c, const unsigned* a, const unsigned* b) {
    asm volatile(
        "mma.sync.aligned.m16n8k16.row.col.f32.f16.f16.f32 "
        "{%0,%1,%2,%3}, {%4,%5,%6,%7}, {%8,%9}, {%0,%1,%2,%3};"
        : "+f"(c[0]), "+f"(c[1]), "+f"(c[2]), "+f"(c[3])
        : "r"(a[0]), "r"(a[1]), "r"(a[2]), "r"(a[3]), "r"(b[0]), "r"(b[1]));
}

// ---------------- edge aggregation (fp16 in, HADD2 tree, fp32 acc, fp16 out) --
__device__ __forceinline__ float4 h4_to_f4(uint2 u) {
    __half2 h0 = *(__half2*)&u.x;
    __half2 h1 = *(__half2*)&u.y;
    float2 f0 = __half22float2(h0);
    float2 f1 = __half22float2(h1);
    return make_float4(f0.x, f0.y, f1.x, f1.y);
}

__global__ __launch_bounds__(256) void agg_kernel(const __half* __restrict__ xh,
                                                  __half* __restrict__ out) {
    int w = (blockIdx.x * blockDim.x + threadIdx.x) >> 5;
    int lane = threadIdx.x & 31;
    if (w >= NN) return;
    const uint2* xv = (const uint2*)xh;       // 32 uint2 per row (128 halves)
    float4 acc = h4_to_f4(__ldg(&xv[(size_t)w * 32 + lane]));
    int s = g_off[w], e = g_off[w + 1];
    int i = s;
    for (; i + 4 <= e; i += 4) {
        int n0 = __ldg(&g_csr[i + 0]);
        int n1 = __ldg(&g_csr[i + 1]);
        int n2 = __ldg(&g_csr[i + 2]);
        int n3 = __ldg(&g_csr[i + 3]);
        uint2 u0 = __ldg(&xv[(size_t)n0 * 32 + lane]);
        uint2 u1 = __ldg(&xv[(size_t)n1 * 32 + lane]);
        uint2 u2 = __ldg(&xv[(size_t)n2 * 32 + lane]);
        uint2 u3 = __ldg(&xv[(size_t)n3 * 32 + lane]);
        __half2 plo = __hadd2(__hadd2(*(__half2*)&u0.x, *(__half2*)&u1.x),
                              __hadd2(*(__half2*)&u2.x, *(__half2*)&u3.x));
        __half2 phi = __hadd2(__hadd2(*(__half2*)&u0.y, *(__half2*)&u1.y),
                              __hadd2(*(__half2*)&u2.y, *(__half2*)&u3.y));
        float2 flo = __half22float2(plo);
        float2 fhi = __half22float2(phi);
        acc.x += flo.x; acc.y += flo.y; acc.z += fhi.x; acc.w += fhi.y;
    }
    for (; i < e; i++) {
        int nb = __ldg(&g_csr[i]);
        float4 v = h4_to_f4(__ldg(&xv[(size_t)nb * 32 + lane]));
        acc.x += v.x; acc.y += v.y; acc.z += v.z; acc.w += v.w;
    }
    __half2 p0 = __floats2half2_rn(acc.x, acc.y);
    __half2 p1 = __floats2half2_rn(acc.z, acc.w);
    uint2 o;
    o.x = *reinterpret_cast<unsigned*>(&p0);
    o.y = *reinterpret_cast<unsigned*>(&p1);
    ((uint2*)out)[(size_t)w * 32 + lane] = o;
}

// ---------------- fp16 tensor-core GEMM, M-tile 128 (A always fp16) ----------
// PRE_BN:  per-column affine + relu applied while staging A
// OUT_RELU / STATS / OUT_HALF as before. Accumulation fp32.
template <bool PRE_BN, bool OUT_RELU, bool STATS, bool OUT_HALF>
__global__ __launch_bounds__(256) void gemm128h_kernel(
    const __half* __restrict__ A, const __half* __restrict__ WT,
    const float* __restrict__ bias,
    const float* __restrict__ scale, const float* __restrict__ shift,
    float* __restrict__ C, __half* __restrict__ Ch, int M) {
    extern __shared__ float smemf[];
    unsigned* As = (unsigned*)smemf;          // MT x LDH (uint32 = 2 halves)
    unsigned* Bs = As + MT * LDH;             // 128 x LDH (n-major: [n][k])
    int tid = threadIdx.x;
    int r0 = blockIdx.x * MT;

    // Bs: coalesced uint4 copy of pre-transposed fp16 W^T (2048 uint4)
    #pragma unroll
    for (int i = 0; i < 8; i++) {
        int idx4 = tid + i * 256;        // 0..2047
        uint4 u = ((const uint4*)WT)[idx4];
        int n = idx4 >> 4, koff = (idx4 & 15) * 4;
        *(uint4*)&Bs[n * LDH + koff] = u;
    }
    // As: fp16 rows (2048 uint4); optional fused BN affine + relu
    #pragma unroll
    for (int i = 0; i < 8; i++) {
        int idx4 = tid + i * 256;        // 0..2047
        int row = idx4 >> 4, q4 = idx4 & 15;
        uint4 u = make_uint4(0u, 0u, 0u, 0u);
        if (r0 + row < M)
            u = ((const uint4*)(A + (size_t)(r0 + row) * 128))[q4];
        if (PRE_BN) {
            int c = q4 * 8;
            float2 f0 = __half22float2(*(__half2*)&u.x);
            float2 f1 = __half22float2(*(__half2*)&u.y);
            float2 f2 = __half22float2(*(__half2*)&u.z);
            float2 f3 = __half22float2(*(__half2*)&u.w);
            f0.x = fmaxf(f0.x * __ldg(&scale[c + 0]) + __ldg(&shift[c + 0]), 0.f);
            f0.y = fmaxf(f0.y * __ldg(&scale[c + 1]) + __ldg(&shift[c + 1]), 0.f);
            f1.x = fmaxf(f1.x * __ldg(&scale[c + 2]) + __ldg(&shift[c + 2]), 0.f);
            f1.y = fmaxf(f1.y * __ldg(&scale[c + 3]) + __ldg(&shift[c + 3]), 0.f);
            f2.x = fmaxf(f2.x * __ldg(&scale[c + 4]) + __ldg(&shift[c + 4]), 0.f);
            f2.y = fmaxf(f2.y * __ldg(&scale[c + 5]) + __ldg(&shift[c + 5]), 0.f);
            f3.x = fmaxf(f3.x * __ldg(&scale[c + 6]) + __ldg(&shift[c + 6]), 0.f);
            f3.y = fmaxf(f3.y * __ldg(&scale[c + 7]) + __ldg(&shift[c + 7]), 0.f);
            __half2 p0 = __floats2half2_rn(f0.x, f0.y);
            __half2 p1 = __floats2half2_rn(f1.x, f1.y);
            __half2 p2 = __floats2half2_rn(f2.x, f2.y);
            __half2 p3 = __floats2half2_rn(f3.x, f3.y);
            u.x = *reinterpret_cast<unsigned*>(&p0);
            u.y = *reinterpret_cast<unsigned*>(&p1);
            u.z = *reinterpret_cast<unsigned*>(&p2);
            u.w = *reinterpret_cast<unsigned*>(&p3);
        }
        *(uint4*)&As[row * LDH + q4 * 4] = u;
    }
    __syncthreads();

    int wid = tid >> 5, lane = tid & 31;
    int wm = wid >> 2, wn = wid & 3;     // 2 (M) x 4 (N) warps; warp tile 64x32
    int gid = lane >> 2, qid = lane & 3;

    float c[4][4][4];
    #pragma unroll
    for (int mi = 0; mi < 4; mi++)
        #pragma unroll
        for (int ni = 0; ni < 4; ni++)
            #pragma unroll
            for (int j = 0; j < 4; j++) c[mi][ni][j] = 0.f;

    #pragma unroll
    for (int kk = 0; kk < 8; kk++) {
        int k0 = kk * 8;                 // uint32 offset = 16 halves
        unsigned a[4][4];
        #pragma unroll
        for (int mi = 0; mi < 4; mi++) {
            int r = wm * 64 + mi * 16 + gid;
            a[mi][0] = As[r * LDH + k0 + qid];
            a[mi][1] = As[(r + 8) * LDH + k0 + qid];
            a[mi][2] = As[r * LDH + k0 + 4 + qid];
            a[mi][3] = As[(r + 8) * LDH + k0 + 4 + qid];
        }
        unsigned b[4][2];
        #pragma unroll
        for (int ni = 0; ni < 4; ni++) {
            int n = wn * 32 + ni * 8 + gid;
            b[ni][0] = Bs[n * LDH + k0 + qid];
            b[ni][1] = Bs[n * LDH + k0 + 4 + qid];
        }
        #pragma unroll
        for (int mi = 0; mi < 4; mi++)
            #pragma unroll
            for (int ni = 0; ni < 4; ni++)
                mma_f16(c[mi][ni], a[mi], b[ni]);
    }

    // ---- epilogue: bias (+relu), stores; optional column-stat partials ----
    float sarr[8], qarr[8];
    if (STATS) {
        #pragma unroll
        for (int t = 0; t < 8; t++) { sarr[t] = 0.f; qarr[t] = 0.f; }
    }
    #pragma unroll
    for (int ni = 0; ni < 4; ni++) {
        int col = wn * 32 + ni * 8 + 2 * qid;
        float b0 = __ldg(&bias[col]);
        float b1 = __ldg(&bias[col + 1]);
        #pragma unroll
        for (int mi = 0; mi < 4; mi++) {
            int gr = r0 + wm * 64 + mi * 16 + gid;
            float o0 = c[mi][ni][0] + b0;
            float o1 = c[mi][ni][1] + b1;
            float o2 = c[mi][ni][2] + b0;
            float o3 = c[mi][ni][3] + b1;
            if (OUT_RELU) {
                o0 = fmaxf(o0, 0.f); o1 = fmaxf(o1, 0.f);
                o2 = fmaxf(o2, 0.f); o3 = fmaxf(o3, 0.f);
            }
            if (gr < M) {
                if (OUT_HALF)
                    ((__half2*)Ch)[(size_t)gr * 64 + (col >> 1)] = __floats2half2_rn(o0, o1);
                else
                    *(float2*)(C + (size_t)gr * 128 + col) = make_float2(o0, o1);
                if (STATS) {
                    sarr[ni * 2 + 0] += o0; qarr[ni * 2 + 0] += o0 * o0;
                    sarr[ni * 2 + 1] += o1; qarr[ni * 2 + 1] += o1 * o1;
                }
            }
            if (gr + 8 < M) {
                if (OUT_HALF)
                    ((__half2*)Ch)[(size_t)(gr + 8) * 64 + (col >> 1)] = __floats2half2_rn(o2, o3);
                else
                    *(float2*)(C + (size_t)(gr + 8) * 128 + col) = make_float2(o2, o3);
                if (STATS) {
                    sarr[ni * 2 + 0] += o2; qarr[ni * 2 + 0] += o2 * o2;
                    sarr[ni * 2 + 1] += o3; qarr[ni * 2 + 1] += o3 * o3;
                }
            }
        }
    }

    if (STATS) {
        // reduce over gid lanes (same qid): butterfly masks 4,8,16 (deterministic)
        #pragma unroll
        for (int t = 0; t < 8; t++) {
            #pragma unroll
            for (int m = 4; m <= 16; m <<= 1) {
                sarr[t] += __shfl_xor_sync(0xffffffffu, sarr[t], m);
                qarr[t] += __shfl_xor_sync(0xffffffffu, qarr[t], m);
            }
        }
        __syncthreads();                 // done reading As/Bs; reuse as scratch
        float* sS = smemf;               // [2][128]
        float* sQ = smemf + 256;         // [2][128]
        if (gid == 0) {
            #pragma unroll
            for (int t = 0; t < 8; t++) {
                int col = wn * 32 + (t >> 1) * 8 + 2 * qid + (t & 1);
                sS[wm * 128 + col] = sarr[t];
                sQ[wm * 128 + col] = qarr[t];
            }
        }
        __syncthreads();
        if (tid < 128) {
            g_psum[blockIdx.x * 128 + tid] = sS[tid] + sS[128 + tid];
            g_psq[blockIdx.x * 128 + tid] = sQ[tid] + sQ[128 + tid];
        }
    }
}

// ---------------- BN finalize over GB1 partials (deterministic) ----------------
__global__ void bnfinalize_kernel(const float* __restrict__ gamma,
                                  const float* __restrict__ beta) {
    __shared__ float ss[8][128];
    __shared__ float qq[8][128];
    int c = threadIdx.x & 127;
    int chunk = threadIdx.x >> 7;    // 0..7
    float s = 0.f, q = 0.f;
    for (int i = chunk; i < GB1; i += 8) {
        s += g_psum[i * 128 + c];
        q += g_psq[i * 128 + c];
    }
    ss[chunk][c] = s;
    qq[chunk][c] = q;
    __syncthreads();
    if (threadIdx.x < 128) {
        float S = 0.f, Qv = 0.f;
        #pragma unroll
        for (int k = 0; k < 8; k++) { S += ss[k][c]; Qv += qq[k][c]; }
        float mu = S / (float)NN;
        float var = Qv / (float)NN - mu * mu;
        float sc = gamma[c] * rsqrtf(var + BN_EPS);
        g_scale[c] = sc;
        g_shift[c] = beta[c] - mu * sc;
    }
}

// ---------------- fused pooling + head MLP (block per graph) ----------------
__device__ __forceinline__ int lower_bound_batch(const void* batch, int key) {
    int lo = 0, hi = NN;
    while (lo < hi) {
        int mid = (lo + hi) >> 1;
        int v = load_idx(batch, mid);
        if (v < key) lo = mid + 1; else hi = mid;
    }
    return lo;
}

__global__ void poolhead_kernel(const float* __restrict__ x, const void* batch,
                                const float* __restrict__ W1,
                                const float* __restrict__ b1,
                                const float* __restrict__ W2,
                                const float* __restrict__ b2,
                                float* __restrict__ out) {
    __shared__ float pr[128];
    __shared__ float h1[128];
    __shared__ int seg[2];
    int g = blockIdx.x;
    int c = threadIdx.x;
    if (c < 2) seg[c] = lower_bound_batch(batch, g + c);
    __syncthreads();
    float acc = 0.f;
    for (int r = seg[0]; r < seg[1]; r++)
        acc += x[(size_t)r * 128 + c];
    pr[c] = acc;
    __syncthreads();
    float s = b1[c];
    #pragma unroll 8
    for (int k = 0; k < 128; k++) s += pr[k] * W1[k * 128 + c];
    h1[c] = fmaxf(s, 0.f);
    __syncthreads();
    if (c < NC) {
        float o = b2[c];
        #pragma unroll 8
        for (int k = 0; k < 128; k++) o += h1[k] * W2[k * NC + c];
        out[g * NC + c] = o;
    }
}

// ---------------- launcher ----------------
extern "C" void kernel_launch(void* const* d_in, const int* in_sizes, int n_in,
                              void* d_out, int out_size) {
    const float* x       = (const float*)d_in[0];
    const void*  ei      = d_in[1];
    const void*  batch   = d_in[2];
    const float* conv_W1 = (const float*)d_in[3];
    const float* conv_b1 = (const float*)d_in[4];
    const float* conv_g  = (const float*)d_in[5];
    const float* conv_bt = (const float*)d_in[6];
    const float* conv_W2 = (const float*)d_in[7];
    const float* conv_b2 = (const float*)d_in[8];
    const float* head_W1 = (const float*)d_in[9];
    const float* head_b1 = (const float*)d_in[10];
    const float* head_W2 = (const float*)d_in[11];
    const float* head_b2 = (const float*)d_in[12];
    float* out = (float*)d_out;

    float *P, *scale, *shift;
    __half *Q, *R, *H, *WT;
    cudaGetSymbolAddress((void**)&P, g_P);
    cudaGetSymbolAddress((void**)&Q, g_Q);
    cudaGetSymbolAddress((void**)&R, g_R);
    cudaGetSymbolAddress((void**)&H, g_H);
    cudaGetSymbolAddress((void**)&WT, g_WT);
    cudaGetSymbolAddress((void**)&scale, g_scale);
    cudaGetSymbolAddress((void**)&shift, g_shift);

    const int SMEM = (MT + 128) * LDH * 4;   // 69632 B
    cudaFuncSetAttribute(gemm128h_kernel<false, false, true, true>,
                         cudaFuncAttributeMaxDynamicSharedMemorySize, SMEM);
    cudaFuncSetAttribute(gemm128h_kernel<true, true, false, true>,
                         cudaFuncAttributeMaxDynamicSharedMemorySize, SMEM);
    cudaFuncSetAttribute(gemm128h_kernel<true, true, false, false>,
                         cudaFuncAttributeMaxDynamicSharedMemorySize, SMEM);

    // launch 0: zero counts + x->fp16 + detect
    zero_prep_kernel<<<(NN * FD / 2 + 255) / 256, 256>>>(
        (const unsigned*)ei, (const float2*)x, (__half2*)H);
    // launch 1: degree count + W transpose
    count_kernel<<<NE / 256 + 160, 256>>>(ei, conv_W1, conv_W2);
    scan_reduce_kernel<<<SCAN_B, 1024>>>();
    scan_final_kernel<<<SCAN_B, 1024>>>();
    fill_kernel<<<NE / 256, 256>>>(ei);

    for (int l = 0; l < NL; l++) {
        // R = fp16( H + sum_neighbors H )  [HADD2 tree, fp32 carry]
        agg_kernel<<<(NN * 32 + 255) / 256, 256>>>(H, R);
        // Q = fp16( R @ W1 + b1 ), with fused fp32 column stats
        gemm128h_kernel<false, false, true, true><<<GB1, 256, SMEM>>>(
            R, WT + (size_t)l * 16384, conv_b1 + l * FD,
            nullptr, nullptr, nullptr, Q, NN);
        bnfinalize_kernel<<<1, 1024>>>(conv_g + l * FD, conv_bt + l * FD);
        // out = relu( relu(BN(Q)) @ W2 + b2 ): fp16 for next gather, fp32 last
        if (l < NL - 1) {
            gemm128h_kernel<true, true, false, true><<<GB1, 256, SMEM>>>(
                Q, WT + (size_t)(5 + l) * 16384, conv_b2 + l * FD,
                scale, shift, nullptr, H, NN);
        } else {
            gemm128h_kernel<true, true, false, false><<<GB1, 256, SMEM>>>(
                Q, WT + (size_t)(5 + l) * 16384, conv_b2 + l * FD,
                scale, shift, P, nullptr, NN);
        }
    }

    poolhead_kernel<<<NG, 128>>>(P, batch, head_W1, head_b1, head_W2, head_b2, out);
}